// round 3
// baseline (speedup 1.0000x reference)
#include <cuda_runtime.h>
#include <math.h>

#define NN 100000
#define EE 600000
#define GG 512
#define HH 128
#define KP0 80          // layer0 K padded (74 -> 80)
#define KR0 74
#define SCAN_B 512
#define NSB ((NN + SCAN_B - 1) / SCAN_B)   // 196

// ---- scratch (device globals; no allocation allowed) ----
__device__ float d_h0[NN * KP0];
__device__ float d_h1[NN * HH];
__device__ float d_agg[NN * HH];
__device__ float d_invdeg[NN];
__device__ int   d_degi[NN];
__device__ int   d_cursor[NN];
__device__ int   d_rowstart[NN + 1];
__device__ int   d_eid[EE];
__device__ int   d_bsum[NSB];
__device__ int   d_boff[NSB];
__device__ float d_psum[GG * HH];
__device__ float d_pmax[GG * HH];
__device__ float d_cnt[GG];

// ---- f32x2 packed helpers ----
__device__ __forceinline__ unsigned long long pack2(float lo, float hi) {
    unsigned long long u;
    asm("mov.b64 %0, {%1, %2};" : "=l"(u) : "f"(lo), "f"(hi));
    return u;
}
__device__ __forceinline__ void unpack2(unsigned long long u, float& lo, float& hi) {
    asm("mov.b64 {%0, %1}, %2;" : "=f"(lo), "=f"(hi) : "l"(u));
}
__device__ __forceinline__ void ffma2(unsigned long long& d,
                                      unsigned long long a,
                                      unsigned long long b) {
    asm("fma.rn.f32x2 %0, %1, %2, %0;" : "+l"(d) : "l"(a), "l"(b));
}

// ---------------------------------------------------------------------------
__global__ void k_init0() {
    int i = blockIdx.x * blockDim.x + threadIdx.x;
    if (i < NN) { d_degi[i] = 0; d_cursor[i] = 0; }
    if (i < GG * HH) { d_psum[i] = 0.f; d_pmax[i] = __int_as_float(0xFF800000); }
    if (i < GG) d_cnt[i] = 0.f;
}

__global__ void k_build_h0(const float* __restrict__ x,
                           const float* __restrict__ xd,
                           const int* __restrict__ st,
                           const float* __restrict__ emb) {
    int idx = blockIdx.x * blockDim.x + threadIdx.x;
    if (idx >= NN * KP0) return;
    int n = idx / KP0;
    int j = idx - n * KP0;
    float v;
    if (j < 60)      v = x[n * 60 + j];
    else if (j < 62) v = xd[n * 2 + (j - 60)];
    else if (j < 74) v = emb[st[n] * 12 + (j - 62)];
    else             v = 0.f;   // pad
    d_h0[idx] = v;
}

__global__ void k_deg(const int* __restrict__ dst) {
    int e = blockIdx.x * blockDim.x + threadIdx.x;
    if (e < EE) atomicAdd(&d_degi[dst[e]], 1);
}

__global__ void __launch_bounds__(SCAN_B)
k_scan1() {
    __shared__ int sc[SCAN_B];
    int tid = threadIdx.x;
    int i = blockIdx.x * SCAN_B + tid;
    int v = (i < NN) ? d_degi[i] : 0;
    sc[tid] = v;
    __syncthreads();
#pragma unroll
    for (int off = 1; off < SCAN_B; off <<= 1) {
        int t = (tid >= off) ? sc[tid - off] : 0;
        __syncthreads();
        sc[tid] += t;
        __syncthreads();
    }
    if (i < NN) {
        d_rowstart[i] = sc[tid] - v;
        d_invdeg[i] = 1.f / fmaxf((float)v, 1.f);
    }
    if (tid == SCAN_B - 1) d_bsum[blockIdx.x] = sc[tid];
}

__global__ void k_scan2() {
    if (threadIdx.x == 0 && blockIdx.x == 0) {
        int run = 0;
        for (int b = 0; b < NSB; b++) { d_boff[b] = run; run += d_bsum[b]; }
        d_rowstart[NN] = EE;
    }
}

__global__ void k_scan3() {
    int i = blockIdx.x * blockDim.x + threadIdx.x;
    if (i < NN) d_rowstart[i] += d_boff[i / SCAN_B];
}

__global__ void k_fill(const int* __restrict__ src, const int* __restrict__ dst) {
    int e = blockIdx.x * blockDim.x + threadIdx.x;
    if (e >= EE) return;
    int dn = dst[e];
    int pos = d_rowstart[dn] + atomicAdd(&d_cursor[dn], 1);
    d_eid[pos] = src[e];
}

// gather aggregation: one warp per node, float4 lanes; writes agg * invdeg.
template <int KP>
__global__ void __launch_bounds__(128)
k_gatherv(const float* __restrict__ h) {
    int n = blockIdx.x * 4 + (threadIdx.x >> 5);
    int lane = threadIdx.x & 31;
    if (n >= NN) return;
    constexpr int C4 = KP / 4;
    if (lane >= C4) return;
    int s = d_rowstart[n];
    int e = d_rowstart[n + 1];
    float4 acc = make_float4(0.f, 0.f, 0.f, 0.f);
    for (int j = s; j < e; j++) {
        int id = d_eid[j];
        float4 v = *(const float4*)&h[(size_t)id * KP + lane * 4];
        acc.x += v.x; acc.y += v.y; acc.z += v.z; acc.w += v.w;
    }
    float inv = d_invdeg[n];
    acc.x *= inv; acc.y *= inv; acc.z *= inv; acc.w *= inv;
    *(float4*)&d_agg[(size_t)n * KP + lane * 4] = acc;
}

// Fused tiled GEMM: C = [agg | h] @ [Wl ; Wr] + bl, then LayerNorm, ReLU,
// then either store (layer0) or fused graph pooling (layer1).
// Block: 256 threads, tile 64 nodes x 128 outputs, BK=16, f32x2 packed FMA.
template <int KP, int KREAL, bool POOL>
__global__ void __launch_bounds__(256)
k_sage2(const float* __restrict__ Wl, const float* __restrict__ bl,
        const float* __restrict__ Wr, const float* __restrict__ g,
        const float* __restrict__ bn, const float* __restrict__ agg_,
        const float* __restrict__ hin, float* __restrict__ hout,
        const int* __restrict__ batch) {
    __shared__ float sA[16 * 68];        // [k][m], padded stride 68
    __shared__ float sB[16 * 256];       // [k][o] duplicated pairs (f32x2-ready)

    const int tid = threadIdx.x;
    const int tx = tid & 15;             // output group: o0 = tx*8
    const int ty = tid >> 4;             // node group: m = ty*4 + 0..3
    const int n0 = blockIdx.x * 64;
    const int o0 = tx * 8;

    // bias-initialized packed accumulators: acc[pair][out]
    float4 b0v = *(const float4*)&bl[o0];
    float4 b1v = *(const float4*)&bl[o0 + 4];
    float bj[8] = {b0v.x, b0v.y, b0v.z, b0v.w, b1v.x, b1v.y, b1v.z, b1v.w};
    unsigned long long acc[2][8];
#pragma unroll
    for (int p = 0; p < 2; p++)
#pragma unroll
        for (int j = 0; j < 8; j++) acc[p][j] = pack2(bj[j], bj[j]);

    const int mload = tid >> 2;          // 0..63
    const int kq = (tid & 3) * 4;        // 0,4,8,12
    const int rowl = n0 + mload;
    constexpr int NC = 2 * KP / 16;

    for (int c = 0; c < NC; c++) {
        const int kc = c * 16;
        // ---- stage A tile (transposed) ----
        {
            const float* base = (kc < KP) ? agg_ : hin;
            const int col = ((kc < KP) ? kc : kc - KP) + kq;
            float4 v = make_float4(0.f, 0.f, 0.f, 0.f);
            if (rowl < NN) v = *(const float4*)&base[(size_t)rowl * KP + col];
            sA[(kq + 0) * 68 + mload] = v.x;
            sA[(kq + 1) * 68 + mload] = v.y;
            sA[(kq + 2) * 68 + mload] = v.z;
            sA[(kq + 3) * 68 + mload] = v.w;
        }
        // ---- stage B tile (duplicated for f32x2 broadcast) ----
        {
            const int o4 = (tid & 31) * 4;
#pragma unroll
            for (int kk = 0; kk < 16; kk += 8) {
                const int k = (tid >> 5) + kk;
                const int kg = kc + k;
                const float* W = (kg < KP) ? Wl : Wr;
                const int row = (kg < KP) ? kg : kg - KP;
                float4 w = make_float4(0.f, 0.f, 0.f, 0.f);
                if (row < KREAL) w = *(const float4*)&W[(size_t)row * HH + o4];
                float* dp = &sB[(k * HH + o4) * 2];
                *(float4*)dp       = make_float4(w.x, w.x, w.y, w.y);
                *(float4*)(dp + 4) = make_float4(w.z, w.z, w.w, w.w);
            }
        }
        __syncthreads();
        // ---- compute ----
#pragma unroll
        for (int k = 0; k < 16; k++) {
            ulonglong2 av = *(const ulonglong2*)&sA[k * 68 + ty * 4];
            const ulonglong2* bp = (const ulonglong2*)&sB[(k * HH + o0) * 2];
            ulonglong2 bv0 = bp[0], bv1 = bp[1], bv2 = bp[2], bv3 = bp[3];
            ffma2(acc[0][0], av.x, bv0.x); ffma2(acc[1][0], av.y, bv0.x);
            ffma2(acc[0][1], av.x, bv0.y); ffma2(acc[1][1], av.y, bv0.y);
            ffma2(acc[0][2], av.x, bv1.x); ffma2(acc[1][2], av.y, bv1.x);
            ffma2(acc[0][3], av.x, bv1.y); ffma2(acc[1][3], av.y, bv1.y);
            ffma2(acc[0][4], av.x, bv2.x); ffma2(acc[1][4], av.y, bv2.x);
            ffma2(acc[0][5], av.x, bv2.y); ffma2(acc[1][5], av.y, bv2.y);
            ffma2(acc[0][6], av.x, bv3.x); ffma2(acc[1][6], av.y, bv3.x);
            ffma2(acc[0][7], av.x, bv3.y); ffma2(acc[1][7], av.y, bv3.y);
        }
        __syncthreads();
    }

    // ---- epilogue: unpack, LayerNorm (per node across 16 tx lanes), ReLU ----
    float y[4][8];
#pragma unroll
    for (int p = 0; p < 2; p++)
#pragma unroll
        for (int j = 0; j < 8; j++) {
            float lo, hi;
            unpack2(acc[p][j], lo, hi);
            y[2 * p][j] = lo;
            y[2 * p + 1][j] = hi;
        }

    float4 g0v = *(const float4*)&g[o0];
    float4 g1v = *(const float4*)&g[o0 + 4];
    float4 n0v = *(const float4*)&bn[o0];
    float4 n1v = *(const float4*)&bn[o0 + 4];
    float gam[8] = {g0v.x, g0v.y, g0v.z, g0v.w, g1v.x, g1v.y, g1v.z, g1v.w};
    float bet[8] = {n0v.x, n0v.y, n0v.z, n0v.w, n1v.x, n1v.y, n1v.z, n1v.w};

#pragma unroll
    for (int mi = 0; mi < 4; mi++) {
        float s = 0.f;
#pragma unroll
        for (int j = 0; j < 8; j++) s += y[mi][j];
#pragma unroll
        for (int off = 1; off < 16; off <<= 1) s += __shfl_xor_sync(~0u, s, off);
        float mu = s * (1.f / HH);
        float s2 = 0.f;
#pragma unroll
        for (int j = 0; j < 8; j++) { float d = y[mi][j] - mu; s2 += d * d; }
#pragma unroll
        for (int off = 1; off < 16; off <<= 1) s2 += __shfl_xor_sync(~0u, s2, off);
        float rstd = rsqrtf(s2 * (1.f / HH) + 1e-5f);

        int n = n0 + ty * 4 + mi;
        if (n < NN) {
            if (POOL) {
                int b = batch[n];
                float* ps = &d_psum[b * HH + o0];
                int*   pm = (int*)&d_pmax[b * HH + o0];
#pragma unroll
                for (int j = 0; j < 8; j++) {
                    float v = fmaxf((y[mi][j] - mu) * rstd * gam[j] + bet[j], 0.f);
                    atomicAdd(ps + j, v);
                    atomicMax(pm + j, __float_as_int(v));
                }
            } else {
                float v[8];
#pragma unroll
                for (int j = 0; j < 8; j++)
                    v[j] = fmaxf((y[mi][j] - mu) * rstd * gam[j] + bet[j], 0.f);
                *(float4*)&hout[(size_t)n * HH + o0]     = make_float4(v[0], v[1], v[2], v[3]);
                *(float4*)&hout[(size_t)n * HH + o0 + 4] = make_float4(v[4], v[5], v[6], v[7]);
            }
        }
    }
}

__global__ void k_cnt(const int* __restrict__ batch) {
    int n = blockIdx.x * blockDim.x + threadIdx.x;
    if (n < NN) atomicAdd(&d_cnt[batch[n]], 1.f);
}

__global__ void __launch_bounds__(64)
k_mlp(const float* __restrict__ Wf0, const float* __restrict__ bf0,
      const float* __restrict__ Wf1, const float* __restrict__ bf1,
      const float* __restrict__ Wf2, const float* __restrict__ bf2,
      float* __restrict__ out) {
    __shared__ float z[2 * HH];
    __shared__ float t1[50];
    __shared__ float t2[50];
    int gg = blockIdx.x;
    int t = threadIdx.x;

    float c = fmaxf(d_cnt[gg], 1.f);
    for (int d = t; d < 2 * HH; d += 64)
        z[d] = (d < HH) ? d_psum[gg * HH + d] / c : d_pmax[gg * HH + (d - HH)];
    __syncthreads();

    if (t < 50) {
        float s = bf0[t];
        for (int k = 0; k < 2 * HH; k++) s += z[k] * Wf0[k * 50 + t];
        t1[t] = fmaxf(s, 0.f);
    }
    __syncthreads();
    if (t < 50) {
        float s = bf1[t];
        for (int k = 0; k < 50; k++) s += t1[k] * Wf1[k * 50 + t];
        t2[t] = fmaxf(s, 0.f);
    }
    __syncthreads();
    if (t < 10) {
        float s = bf2[t];
        for (int k = 0; k < 50; k++) s += t2[k] * Wf2[k * 10 + t];
        out[gg * 10 + t] = fmaxf(s, 0.f);
    }
}

// ---------------------------------------------------------------------------
static inline int cdiv(long long a, int b) { return (int)((a + b - 1) / b); }

extern "C" void kernel_launch(void* const* d_in, const int* in_sizes, int n_in,
                              void* d_out, int out_size) {
    const float* x      = (const float*)d_in[0];
    const float* xdims  = (const float*)d_in[1];
    const int*   st     = (const int*)d_in[2];
    const int*   ei     = (const int*)d_in[3];
    const int*   batch  = (const int*)d_in[4];
    const float* emb    = (const float*)d_in[5];
    const float* Wl0 = (const float*)d_in[6];
    const float* bl0 = (const float*)d_in[7];
    const float* Wr0 = (const float*)d_in[8];
    const float* g0  = (const float*)d_in[9];
    const float* bn0 = (const float*)d_in[10];
    const float* Wl1 = (const float*)d_in[11];
    const float* bl1 = (const float*)d_in[12];
    const float* Wr1 = (const float*)d_in[13];
    const float* g1  = (const float*)d_in[14];
    const float* bn1 = (const float*)d_in[15];
    const float* Wf0 = (const float*)d_in[16];
    const float* bf0 = (const float*)d_in[17];
    const float* Wf1 = (const float*)d_in[18];
    const float* bf1 = (const float*)d_in[19];
    const float* Wf2 = (const float*)d_in[20];
    const float* bf2 = (const float*)d_in[21];
    float* out = (float*)d_out;

    const int* src = ei;
    const int* dst = ei + EE;

    float* p_h0 = nullptr;
    float* p_h1 = nullptr;
    float* p_agg = nullptr;
    cudaGetSymbolAddress((void**)&p_h0, d_h0);
    cudaGetSymbolAddress((void**)&p_h1, d_h1);
    cudaGetSymbolAddress((void**)&p_agg, d_agg);

    // init + node features + CSR build (shared by both layers)
    k_init0<<<cdiv(NN, 256), 256>>>();
    k_build_h0<<<cdiv((long long)NN * KP0, 256), 256>>>(x, xdims, st, emb);
    k_deg<<<cdiv(EE, 256), 256>>>(dst);
    k_scan1<<<NSB, SCAN_B>>>();
    k_scan2<<<1, 32>>>();
    k_scan3<<<cdiv(NN, 256), 256>>>();
    k_fill<<<cdiv(EE, 256), 256>>>(src, dst);
    k_cnt<<<cdiv(NN, 256), 256>>>(batch);

    // ---- layer 0 ----
    k_gatherv<KP0><<<cdiv(NN, 4), 128>>>(p_h0);
    k_sage2<KP0, KR0, false><<<cdiv(NN, 64), 256>>>(
        Wl0, bl0, Wr0, g0, bn0, p_agg, p_h0, p_h1, nullptr);

    // ---- layer 1 (pooling fused into epilogue) ----
    k_gatherv<HH><<<cdiv(NN, 4), 128>>>(p_h1);
    k_sage2<HH, HH, true><<<cdiv(NN, 64), 256>>>(
        Wl1, bl1, Wr1, g1, bn1, p_agg, p_h1, nullptr, batch);

    // ---- MLP head ----
    k_mlp<<<GG, 64>>>(Wf0, bf0, Wf1, bf1, Wf2, bf2, out);
}

// round 4
// speedup vs baseline: 2.1551x; 2.1551x over previous
#include <cuda_runtime.h>
#include <math.h>

#define NN 100000
#define EE 600000
#define GG 512
#define HH 128
#define KP0 80          // layer0 K padded (74 -> 80)
#define KR0 74
#define SCAN_B 512
#define NSB ((NN + SCAN_B - 1) / SCAN_B)   // 196

// ---- scratch (device globals; no allocation allowed) ----
__device__ float d_h0[NN * KP0];
__device__ float d_h1[NN * HH];
__device__ float d_agg[NN * HH];
__device__ float d_invdeg[NN];
__device__ int   d_degi[NN];
__device__ int   d_cursor[NN];
__device__ int   d_rowstart[NN + 1];
__device__ int   d_eid[EE];
__device__ int   d_bsum[NSB];
__device__ int   d_boff[NSB];
__device__ float d_psum[GG * HH];
__device__ float d_pmax[GG * HH];
__device__ float d_cnt[GG];

// ---------------------------------------------------------------------------
__global__ void k_init0() {
    int i = blockIdx.x * blockDim.x + threadIdx.x;
    if (i < NN) { d_degi[i] = 0; d_cursor[i] = 0; }
    if (i < GG * HH) { d_psum[i] = 0.f; d_pmax[i] = __int_as_float(0xFF800000); }
    if (i < GG) d_cnt[i] = 0.f;
}

__global__ void k_build_h0(const float* __restrict__ x,
                           const float* __restrict__ xd,
                           const int* __restrict__ st,
                           const float* __restrict__ emb) {
    int idx = blockIdx.x * blockDim.x + threadIdx.x;
    if (idx >= NN * KP0) return;
    int n = idx / KP0;
    int j = idx - n * KP0;
    float v;
    if (j < 60)      v = x[n * 60 + j];
    else if (j < 62) v = xd[n * 2 + (j - 60)];
    else if (j < 74) v = emb[st[n] * 12 + (j - 62)];
    else             v = 0.f;   // pad
    d_h0[idx] = v;
}

__global__ void k_deg(const int* __restrict__ dst) {
    int e = blockIdx.x * blockDim.x + threadIdx.x;
    if (e < EE) atomicAdd(&d_degi[dst[e]], 1);
}

__global__ void __launch_bounds__(SCAN_B)
k_scan1() {
    __shared__ int sc[SCAN_B];
    int tid = threadIdx.x;
    int i = blockIdx.x * SCAN_B + tid;
    int v = (i < NN) ? d_degi[i] : 0;
    sc[tid] = v;
    __syncthreads();
#pragma unroll
    for (int off = 1; off < SCAN_B; off <<= 1) {
        int t = (tid >= off) ? sc[tid - off] : 0;
        __syncthreads();
        sc[tid] += t;
        __syncthreads();
    }
    if (i < NN) {
        d_rowstart[i] = sc[tid] - v;
        d_invdeg[i] = 1.f / fmaxf((float)v, 1.f);
    }
    if (tid == SCAN_B - 1) d_bsum[blockIdx.x] = sc[tid];
}

__global__ void k_scan2() {
    if (threadIdx.x == 0 && blockIdx.x == 0) {
        int run = 0;
        for (int b = 0; b < NSB; b++) { d_boff[b] = run; run += d_bsum[b]; }
        d_rowstart[NN] = EE;
    }
}

__global__ void k_scan3() {
    int i = blockIdx.x * blockDim.x + threadIdx.x;
    if (i < NN) d_rowstart[i] += d_boff[i / SCAN_B];
}

__global__ void k_fill(const int* __restrict__ src, const int* __restrict__ dst) {
    int e = blockIdx.x * blockDim.x + threadIdx.x;
    if (e >= EE) return;
    int dn = dst[e];
    int pos = d_rowstart[dn] + atomicAdd(&d_cursor[dn], 1);
    d_eid[pos] = src[e];
}

// gather aggregation: one warp per node, float4 lanes; writes agg * invdeg.
template <int KP>
__global__ void __launch_bounds__(128)
k_gatherv(const float* __restrict__ h) {
    int n = blockIdx.x * 4 + (threadIdx.x >> 5);
    int lane = threadIdx.x & 31;
    if (n >= NN) return;
    constexpr int C4 = KP / 4;
    if (lane >= C4) return;
    int s = d_rowstart[n];
    int e = d_rowstart[n + 1];
    float4 acc = make_float4(0.f, 0.f, 0.f, 0.f);
    for (int j = s; j < e; j++) {
        int id = d_eid[j];
        float4 v = *(const float4*)&h[(size_t)id * KP + lane * 4];
        acc.x += v.x; acc.y += v.y; acc.z += v.z; acc.w += v.w;
    }
    float inv = d_invdeg[n];
    acc.x *= inv; acc.y *= inv; acc.z *= inv; acc.w *= inv;
    *(float4*)&d_agg[(size_t)n * KP + lane * 4] = acc;
}

// Fused tiled GEMM: C = [agg | h] @ [Wl ; Wr] + bl -> LayerNorm -> ReLU ->
// store (layer0) or fused graph pooling (layer1).
// 256 threads, tile 64 nodes x 128 outputs, BK=16, scalar fp32 register tile
// (4 nodes x 8 outs per thread), shuffle-only LN.
template <int KP, int KREAL, bool POOL>
__global__ void __launch_bounds__(256)
k_sage3(const float* __restrict__ Wl, const float* __restrict__ bl,
        const float* __restrict__ Wr, const float* __restrict__ g,
        const float* __restrict__ bn, const float* __restrict__ agg_,
        const float* __restrict__ hin, float* __restrict__ hout,
        const int* __restrict__ batch) {
    __shared__ float sA[16 * 68];        // [k][m] transposed, stride 68
    __shared__ float sB[16 * HH];        // [k][o]

    const int tid = threadIdx.x;
    const int tx = tid & 15;             // o0 = tx*8
    const int ty = tid >> 4;             // nodes m0 = ty*4
    const int n0 = blockIdx.x * 64;
    const int o0 = tx * 8;

    float acc[4][8];
    {
        float4 b0v = *(const float4*)&bl[o0];
        float4 b1v = *(const float4*)&bl[o0 + 4];
        float bj[8] = {b0v.x, b0v.y, b0v.z, b0v.w, b1v.x, b1v.y, b1v.z, b1v.w};
#pragma unroll
        for (int mi = 0; mi < 4; mi++)
#pragma unroll
            for (int j = 0; j < 8; j++) acc[mi][j] = bj[j];
    }

    const int mload = tid >> 2;          // 0..63
    const int kq = (tid & 3) * 4;        // 0,4,8,12
    const int rowl = n0 + mload;
    constexpr int NC = 2 * KP / 16;

    for (int c = 0; c < NC; c++) {
        const int kc = c * 16;
        // ---- stage A tile (transposed) ----
        {
            const float* base = (kc < KP) ? agg_ : hin;
            const int col = ((kc < KP) ? kc : kc - KP) + kq;
            float4 v = make_float4(0.f, 0.f, 0.f, 0.f);
            if (rowl < NN) v = *(const float4*)&base[(size_t)rowl * KP + col];
            sA[(kq + 0) * 68 + mload] = v.x;
            sA[(kq + 1) * 68 + mload] = v.y;
            sA[(kq + 2) * 68 + mload] = v.z;
            sA[(kq + 3) * 68 + mload] = v.w;
        }
        // ---- stage B tile ----
        {
            const int o4 = (tid & 31) * 4;
            const int krow = tid >> 5;   // 0..7
#pragma unroll
            for (int kk = 0; kk < 16; kk += 8) {
                const int k = krow + kk;
                const int kg = kc + k;
                const float* W = (kg < KP) ? Wl : Wr;
                const int row = (kg < KP) ? kg : kg - KP;
                float4 w = make_float4(0.f, 0.f, 0.f, 0.f);
                if (row < KREAL) w = *(const float4*)&W[(size_t)row * HH + o4];
                *(float4*)&sB[k * HH + o4] = w;
            }
        }
        __syncthreads();
        // ---- compute: 32 FFMA per k per thread ----
#pragma unroll
        for (int k = 0; k < 16; k++) {
            float4 a = *(const float4*)&sA[k * 68 + ty * 4];
            float4 b0 = *(const float4*)&sB[k * HH + o0];
            float4 b1 = *(const float4*)&sB[k * HH + o0 + 4];
            float av[4] = {a.x, a.y, a.z, a.w};
            float bv[8] = {b0.x, b0.y, b0.z, b0.w, b1.x, b1.y, b1.z, b1.w};
#pragma unroll
            for (int mi = 0; mi < 4; mi++)
#pragma unroll
                for (int j = 0; j < 8; j++)
                    acc[mi][j] = fmaf(av[mi], bv[j], acc[mi][j]);
        }
        __syncthreads();
    }

    // ---- epilogue: LayerNorm per node across 16 tx threads (shuffle only) ----
    float4 g0v = *(const float4*)&g[o0];
    float4 g1v = *(const float4*)&g[o0 + 4];
    float4 n0v = *(const float4*)&bn[o0];
    float4 n1v = *(const float4*)&bn[o0 + 4];
    float gam[8] = {g0v.x, g0v.y, g0v.z, g0v.w, g1v.x, g1v.y, g1v.z, g1v.w};
    float bet[8] = {n0v.x, n0v.y, n0v.z, n0v.w, n1v.x, n1v.y, n1v.z, n1v.w};

#pragma unroll
    for (int mi = 0; mi < 4; mi++) {
        float s = 0.f;
#pragma unroll
        for (int j = 0; j < 8; j++) s += acc[mi][j];
#pragma unroll
        for (int off = 1; off < 16; off <<= 1) s += __shfl_xor_sync(~0u, s, off);
        float mu = s * (1.f / HH);
        float s2 = 0.f;
#pragma unroll
        for (int j = 0; j < 8; j++) { float d = acc[mi][j] - mu; s2 += d * d; }
#pragma unroll
        for (int off = 1; off < 16; off <<= 1) s2 += __shfl_xor_sync(~0u, s2, off);
        float rstd = rsqrtf(s2 * (1.f / HH) + 1e-5f);

        int n = n0 + ty * 4 + mi;
        if (n < NN) {
            if (POOL) {
                int b = batch[n];
                float* ps = &d_psum[b * HH + o0];
                int*   pm = (int*)&d_pmax[b * HH + o0];
#pragma unroll
                for (int j = 0; j < 8; j++) {
                    float v = fmaxf((acc[mi][j] - mu) * rstd * gam[j] + bet[j], 0.f);
                    atomicAdd(ps + j, v);
                    atomicMax(pm + j, __float_as_int(v));
                }
            } else {
                float v[8];
#pragma unroll
                for (int j = 0; j < 8; j++)
                    v[j] = fmaxf((acc[mi][j] - mu) * rstd * gam[j] + bet[j], 0.f);
                *(float4*)&hout[(size_t)n * HH + o0]     = make_float4(v[0], v[1], v[2], v[3]);
                *(float4*)&hout[(size_t)n * HH + o0 + 4] = make_float4(v[4], v[5], v[6], v[7]);
            }
        }
    }
}

__global__ void k_cnt(const int* __restrict__ batch) {
    int n = blockIdx.x * blockDim.x + threadIdx.x;
    if (n < NN) atomicAdd(&d_cnt[batch[n]], 1.f);
}

__global__ void __launch_bounds__(64)
k_mlp(const float* __restrict__ Wf0, const float* __restrict__ bf0,
      const float* __restrict__ Wf1, const float* __restrict__ bf1,
      const float* __restrict__ Wf2, const float* __restrict__ bf2,
      float* __restrict__ out) {
    __shared__ float z[2 * HH];
    __shared__ float t1[50];
    __shared__ float t2[50];
    int gg = blockIdx.x;
    int t = threadIdx.x;

    float c = fmaxf(d_cnt[gg], 1.f);
    for (int d = t; d < 2 * HH; d += 64)
        z[d] = (d < HH) ? d_psum[gg * HH + d] / c : d_pmax[gg * HH + (d - HH)];
    __syncthreads();

    if (t < 50) {
        float s = bf0[t];
        for (int k = 0; k < 2 * HH; k++) s += z[k] * Wf0[k * 50 + t];
        t1[t] = fmaxf(s, 0.f);
    }
    __syncthreads();
    if (t < 50) {
        float s = bf1[t];
        for (int k = 0; k < 50; k++) s += t1[k] * Wf1[k * 50 + t];
        t2[t] = fmaxf(s, 0.f);
    }
    __syncthreads();
    if (t < 10) {
        float s = bf2[t];
        for (int k = 0; k < 50; k++) s += t2[k] * Wf2[k * 10 + t];
        out[gg * 10 + t] = fmaxf(s, 0.f);
    }
}

// ---------------------------------------------------------------------------
static inline int cdiv(long long a, int b) { return (int)((a + b - 1) / b); }

extern "C" void kernel_launch(void* const* d_in, const int* in_sizes, int n_in,
                              void* d_out, int out_size) {
    const float* x      = (const float*)d_in[0];
    const float* xdims  = (const float*)d_in[1];
    const int*   st     = (const int*)d_in[2];
    const int*   ei     = (const int*)d_in[3];
    const int*   batch  = (const int*)d_in[4];
    const float* emb    = (const float*)d_in[5];
    const float* Wl0 = (const float*)d_in[6];
    const float* bl0 = (const float*)d_in[7];
    const float* Wr0 = (const float*)d_in[8];
    const float* g0  = (const float*)d_in[9];
    const float* bn0 = (const float*)d_in[10];
    const float* Wl1 = (const float*)d_in[11];
    const float* bl1 = (const float*)d_in[12];
    const float* Wr1 = (const float*)d_in[13];
    const float* g1  = (const float*)d_in[14];
    const float* bn1 = (const float*)d_in[15];
    const float* Wf0 = (const float*)d_in[16];
    const float* bf0 = (const float*)d_in[17];
    const float* Wf1 = (const float*)d_in[18];
    const float* bf1 = (const float*)d_in[19];
    const float* Wf2 = (const float*)d_in[20];
    const float* bf2 = (const float*)d_in[21];
    float* out = (float*)d_out;

    const int* src = ei;
    const int* dst = ei + EE;

    float* p_h0 = nullptr;
    float* p_h1 = nullptr;
    float* p_agg = nullptr;
    cudaGetSymbolAddress((void**)&p_h0, d_h0);
    cudaGetSymbolAddress((void**)&p_h1, d_h1);
    cudaGetSymbolAddress((void**)&p_agg, d_agg);

    // init + node features + CSR build (shared by both layers)
    k_init0<<<cdiv(NN, 256), 256>>>();
    k_build_h0<<<cdiv((long long)NN * KP0, 256), 256>>>(x, xdims, st, emb);
    k_deg<<<cdiv(EE, 256), 256>>>(dst);
    k_scan1<<<NSB, SCAN_B>>>();
    k_scan2<<<1, 32>>>();
    k_scan3<<<cdiv(NN, 256), 256>>>();
    k_fill<<<cdiv(EE, 256), 256>>>(src, dst);
    k_cnt<<<cdiv(NN, 256), 256>>>(batch);

    // ---- layer 0 ----
    k_gatherv<KP0><<<cdiv(NN, 4), 128>>>(p_h0);
    k_sage3<KP0, KR0, false><<<cdiv(NN, 64), 256>>>(
        Wl0, bl0, Wr0, g0, bn0, p_agg, p_h0, p_h1, nullptr);

    // ---- layer 1 (pooling fused into epilogue) ----
    k_gatherv<HH><<<cdiv(NN, 4), 128>>>(p_h1);
    k_sage3<HH, HH, true><<<cdiv(NN, 64), 256>>>(
        Wl1, bl1, Wr1, g1, bn1, p_agg, p_h1, nullptr, batch);

    // ---- MLP head ----
    k_mlp<<<GG, 64>>>(Wf0, bf0, Wf1, bf1, Wf2, bf2, out);
}

// round 6
// speedup vs baseline: 2.6558x; 1.2323x over previous
#include <cuda_runtime.h>
#include <cuda_bf16.h>
#include <math.h>
#include <stdint.h>

#define NN 100000
#define EE 600000
#define GG 512
#define HH 128
#define KP0 80          // layer0 K padded (74 -> 80)
#define KR0 74
#define SCAN_B 512
#define NSB ((NN + SCAN_B - 1) / SCAN_B)   // 196
#define CS 132          // smem C row stride (floats), 16B-aligned rows

// ---- scratch (device globals; no allocation allowed) ----
__device__ float d_h0[NN * KP0];
__device__ float d_h1[NN * HH];
__device__ float d_agg[NN * HH];
__device__ float d_invdeg[NN];
__device__ int   d_degi[NN];
__device__ int   d_cursor[NN];
__device__ int   d_rowstart[NN + 1];
__device__ int   d_eid[EE];
__device__ int   d_bsum[NSB];
__device__ int   d_boff[NSB];
__device__ float d_psum[GG * HH];
__device__ float d_pmax[GG * HH];
__device__ float d_cnt[GG];

// ============================ helpers ======================================
__device__ __forceinline__ uint32_t smem_u32(const void* p) {
    uint32_t a;
    asm("{ .reg .u64 t; cvta.to.shared.u64 t, %1; cvt.u32.u64 %0, t; }"
        : "=r"(a) : "l"(p));
    return a;
}
__device__ __forceinline__ uint32_t sw128(uint32_t off) { return off ^ ((off >> 3) & 0x70); }
__device__ __forceinline__ uint32_t bpack(__nv_bfloat16 a, __nv_bfloat16 b) {
    return ((uint32_t)__bfloat16_as_ushort(b) << 16) | (uint32_t)__bfloat16_as_ushort(a);
}
__device__ __forceinline__ void ldsm4(uint32_t& r0, uint32_t& r1,
                                      uint32_t& r2, uint32_t& r3, uint32_t addr) {
    asm volatile("ldmatrix.sync.aligned.m8n8.x4.shared.b16 {%0,%1,%2,%3}, [%4];"
                 : "=r"(r0), "=r"(r1), "=r"(r2), "=r"(r3) : "r"(addr));
}
__device__ __forceinline__ void mma16816(float* d, const uint32_t* a,
                                         uint32_t b0, uint32_t b1) {
    asm volatile("mma.sync.aligned.m16n8k16.row.col.f32.bf16.bf16.f32 "
                 "{%0,%1,%2,%3}, {%4,%5,%6,%7}, {%8,%9}, {%0,%1,%2,%3};"
                 : "+f"(d[0]), "+f"(d[1]), "+f"(d[2]), "+f"(d[3])
                 : "r"(a[0]), "r"(a[1]), "r"(a[2]), "r"(a[3]), "r"(b0), "r"(b1));
}

// ===========================================================================
__global__ void k_init0() {
    int i = blockIdx.x * blockDim.x + threadIdx.x;
    if (i < NN) { d_degi[i] = 0; d_cursor[i] = 0; }
    if (i < GG * HH) { d_psum[i] = 0.f; d_pmax[i] = __int_as_float(0xFF800000); }
    if (i < GG) d_cnt[i] = 0.f;
}

__global__ void k_build_h0(const float* __restrict__ x,
                           const float* __restrict__ xd,
                           const int* __restrict__ st,
                           const float* __restrict__ emb) {
    int idx = blockIdx.x * blockDim.x + threadIdx.x;
    if (idx >= NN * KP0) return;
    int n = idx / KP0;
    int j = idx - n * KP0;
    float v;
    if (j < 60)      v = x[n * 60 + j];
    else if (j < 62) v = xd[n * 2 + (j - 60)];
    else if (j < 74) v = emb[st[n] * 12 + (j - 62)];
    else             v = 0.f;
    d_h0[idx] = v;
}

__global__ void k_deg(const int* __restrict__ dst) {
    int e = blockIdx.x * blockDim.x + threadIdx.x;
    if (e < EE) atomicAdd(&d_degi[dst[e]], 1);
}

__global__ void __launch_bounds__(SCAN_B)
k_scan1() {
    __shared__ int sc[SCAN_B];
    int tid = threadIdx.x;
    int i = blockIdx.x * SCAN_B + tid;
    int v = (i < NN) ? d_degi[i] : 0;
    sc[tid] = v;
    __syncthreads();
#pragma unroll
    for (int off = 1; off < SCAN_B; off <<= 1) {
        int t = (tid >= off) ? sc[tid - off] : 0;
        __syncthreads();
        sc[tid] += t;
        __syncthreads();
    }
    if (i < NN) {
        d_rowstart[i] = sc[tid] - v;
        d_invdeg[i] = 1.f / fmaxf((float)v, 1.f);
    }
    if (tid == SCAN_B - 1) d_bsum[blockIdx.x] = sc[tid];
}

__global__ void k_scan2() {
    if (threadIdx.x == 0 && blockIdx.x == 0) {
        int run = 0;
        for (int b = 0; b < NSB; b++) { d_boff[b] = run; run += d_bsum[b]; }
        d_rowstart[NN] = EE;
    }
}

__global__ void k_scan3() {
    int i = blockIdx.x * blockDim.x + threadIdx.x;
    if (i < NN) d_rowstart[i] += d_boff[i / SCAN_B];
}

__global__ void k_fill(const int* __restrict__ src, const int* __restrict__ dst) {
    int e = blockIdx.x * blockDim.x + threadIdx.x;
    if (e >= EE) return;
    int dn = dst[e];
    int pos = d_rowstart[dn] + atomicAdd(&d_cursor[dn], 1);
    d_eid[pos] = src[e];
}

// gather aggregation: one warp per node, float4 lanes; writes agg * invdeg.
template <int KP>
__global__ void __launch_bounds__(128)
k_gatherv(const float* __restrict__ h) {
    int n = blockIdx.x * 4 + (threadIdx.x >> 5);
    int lane = threadIdx.x & 31;
    if (n >= NN) return;
    constexpr int C4 = KP / 4;
    if (lane >= C4) return;
    int s = d_rowstart[n];
    int e = d_rowstart[n + 1];
    float4 acc = make_float4(0.f, 0.f, 0.f, 0.f);
    for (int j = s; j < e; j++) {
        int id = d_eid[j];
        float4 v = *(const float4*)&h[(size_t)id * KP + lane * 4];
        acc.x += v.x; acc.y += v.y; acc.z += v.z; acc.w += v.w;
    }
    float inv = d_invdeg[n];
    acc.x *= inv; acc.y *= inv; acc.z *= inv; acc.w *= inv;
    *(float4*)&d_agg[(size_t)n * KP + lane * 4] = acc;
}

// ===========================================================================
// HMMA fused SAGE layer: C = [agg|h] @ [Wl;Wr] + bl -> LN -> ReLU ->
// store (layer0) or pooled (layer1). bf16 hi/lo 3-MMA split for accuracy.
// Tile 128 nodes x 128 outs, K chunks of 64; 8 warps (2x4 warp grid).
// ===========================================================================
template <int KP, int KREAL, bool POOL>
__global__ void __launch_bounds__(256, 1)
k_sage_hmma(const float* __restrict__ Wl, const float* __restrict__ bl,
            const float* __restrict__ Wr, const float* __restrict__ g,
            const float* __restrict__ bn, const float* __restrict__ agg_,
            const float* __restrict__ hin, float* __restrict__ hout,
            const int* __restrict__ batch) {
    extern __shared__ __align__(128) char smem[];
    constexpr int KT = 2 * KP;
    constexpr int NCH = (KT + 63) / 64;
    const uint32_t sb = smem_u32(smem);
    const int tid = threadIdx.x;
    const int wid = tid >> 5;
    const int lid = tid & 31;
    const int n0 = blockIdx.x * 128;
    const int wm = wid & 1;      // 0..1 -> 64-node half
    const int wn = wid >> 1;     // 0..3 -> 32-out quarter

    const uint32_t AHI = sb, ALO = sb + 16384, BHI = sb + 32768, BLO = sb + 49152;
    float* sC   = (float*)smem;                    // reuses staging after k-loop
    float* s_bl = (float*)(smem + 128 * CS * 4);   // 67584
    float* s_g  = s_bl + 128;
    float* s_bn = s_bl + 256;
    float* s_mu = s_bl + 384;
    float* s_rs = s_bl + 512;
    int*  sbat  = (int*)(s_bl + 640);

    if (tid < 128) {
        s_bl[tid] = bl[tid]; s_g[tid] = g[tid]; s_bn[tid] = bn[tid];
        if (POOL) sbat[tid] = (n0 + tid < NN) ? batch[n0 + tid] : 0;
    }

    float acc[4][4][4];
#pragma unroll
    for (int mt = 0; mt < 4; mt++)
#pragma unroll
        for (int nt = 0; nt < 4; nt++)
#pragma unroll
            for (int j = 0; j < 4; j++) acc[mt][nt][j] = 0.f;

    for (int c = 0; c < NCH; c++) {
        const int kbase = c * 64;
        __syncthreads();
        // ---- stage B chunk: rows = out channel o, cols = k (hi/lo bf16) ----
        for (int idx = tid; idx < 128 * 32; idx += 256) {
            int o = idx & 127, kp = idx >> 7;
            int k0 = kbase + kp * 2;
            float w0 = 0.f, w1 = 0.f;
            if (k0 < KT) {
                const float* W; int r;
                if (k0 < KP) { W = Wl; r = k0; } else { W = Wr; r = k0 - KP; }
                if (r < KREAL)     w0 = W[(size_t)r * HH + o];
                if (r + 1 < KREAL) w1 = W[(size_t)(r + 1) * HH + o];
            }
            __nv_bfloat16 h0 = __float2bfloat16(w0), h1 = __float2bfloat16(w1);
            float l0 = w0 - __bfloat162float(h0), l1 = w1 - __bfloat162float(h1);
            uint32_t sw = sw128((uint32_t)o * 128 + kp * 4);
            *(uint32_t*)(smem + 32768 + sw) = bpack(h0, h1);
            *(uint32_t*)(smem + 49152 + sw) = bpack(__float2bfloat16(l0), __float2bfloat16(l1));
        }
        // ---- stage A chunk: rows = node m, cols = k ----
        for (int idx = tid; idx < 2048; idx += 256) {
            int m = idx >> 4, q = idx & 15;
            int kloc = q * 4, kg = kbase + kloc;
            int n = n0 + m;
            float4 v = make_float4(0.f, 0.f, 0.f, 0.f);
            if (n < NN && kg < KT)
                v = (kg < KP) ? *(const float4*)&agg_[(size_t)n * KP + kg]
                              : *(const float4*)&hin[(size_t)n * KP + kg - KP];
            __nv_bfloat16 a0 = __float2bfloat16(v.x), a1 = __float2bfloat16(v.y);
            __nv_bfloat16 a2 = __float2bfloat16(v.z), a3 = __float2bfloat16(v.w);
            float r0 = v.x - __bfloat162float(a0), r1 = v.y - __bfloat162float(a1);
            float r2 = v.z - __bfloat162float(a2), r3 = v.w - __bfloat162float(a3);
            uint32_t sw = sw128((uint32_t)m * 128 + kloc * 2);
            *(uint2*)(smem + 0     + sw) = make_uint2(bpack(a0, a1), bpack(a2, a3));
            *(uint2*)(smem + 16384 + sw) =
                make_uint2(bpack(__float2bfloat16(r0), __float2bfloat16(r1)),
                           bpack(__float2bfloat16(r2), __float2bfloat16(r3)));
        }
        __syncthreads();
        // ---- compute 4 k16-steps ----
#pragma unroll
        for (int ks = 0; ks < 4; ks++) {
            const int k0 = ks * 16;
            const int kof = k0 + (((lid >> 4) & 1) << 3);
            const int rsub = (lid & 7) + ((lid >> 3) & 1) * 8;

            uint32_t ah[4][4], al[4][4];
#pragma unroll
            for (int mt = 0; mt < 4; mt++) {
                int row = wm * 64 + mt * 16 + rsub;
                uint32_t o = sw128((uint32_t)row * 128 + kof * 2);
                ldsm4(ah[mt][0], ah[mt][1], ah[mt][2], ah[mt][3], AHI + o);
                ldsm4(al[mt][0], al[mt][1], al[mt][2], al[mt][3], ALO + o);
            }
            uint32_t bh[2][4], blo[2][4];
#pragma unroll
            for (int ng = 0; ng < 2; ng++) {
                int rown = wn * 32 + ng * 16 + rsub;
                uint32_t o = sw128((uint32_t)rown * 128 + kof * 2);
                ldsm4(bh[ng][0], bh[ng][1], bh[ng][2], bh[ng][3], BHI + o);
                ldsm4(blo[ng][0], blo[ng][1], blo[ng][2], blo[ng][3], BLO + o);
            }
#pragma unroll
            for (int mt = 0; mt < 4; mt++)
#pragma unroll
                for (int nt = 0; nt < 4; nt++) {
                    int ng = nt >> 1, sel = nt & 1;
                    mma16816(acc[mt][nt], ah[mt], bh[ng][sel], bh[ng][sel + 2]);
                    mma16816(acc[mt][nt], ah[mt], blo[ng][sel], blo[ng][sel + 2]);
                    mma16816(acc[mt][nt], al[mt], bh[ng][sel], bh[ng][sel + 2]);
                }
        }
    }
    __syncthreads();

    // ---- store C frags to smem ----
#pragma unroll
    for (int mt = 0; mt < 4; mt++)
#pragma unroll
        for (int nt = 0; nt < 4; nt++) {
            int r0 = wm * 64 + mt * 16 + (lid >> 2);
            int c0 = wn * 32 + nt * 8 + 2 * (lid & 3);
            sC[r0 * CS + c0]           = acc[mt][nt][0];
            sC[r0 * CS + c0 + 1]       = acc[mt][nt][1];
            sC[(r0 + 8) * CS + c0]     = acc[mt][nt][2];
            sC[(r0 + 8) * CS + c0 + 1] = acc[mt][nt][3];
        }
    __syncthreads();

    // ---- LN stats per node row ----
    if (tid < 128) {
        float sum = 0.f, sq = 0.f;
        for (int cc = 0; cc < 128; cc++) {
            float v = sC[tid * CS + cc] + s_bl[cc];
            sum += v; sq += v * v;
        }
        float mu = sum * (1.f / HH);
        float var = fmaxf(sq * (1.f / HH) - mu * mu, 0.f);
        s_mu[tid] = mu;
        s_rs[tid] = rsqrtf(var + 1e-5f);
    }
    __syncthreads();

    if (POOL) {
        // column pooling with run-length flush (batch sorted)
        if (tid < 128) {
            int vrows = min(128, NN - n0);
            float gc = s_g[tid], bc = s_bn[tid], blc = s_bl[tid];
            float s = 0.f, mx = -__int_as_float(0x7F800000);
            int cur = sbat[0];
            for (int m = 0; m < vrows; m++) {
                int b = sbat[m];
                if (b != cur) {
                    atomicAdd(&d_psum[cur * HH + tid], s);
                    atomicMax((int*)&d_pmax[cur * HH + tid], __float_as_int(mx));
                    s = 0.f; mx = -__int_as_float(0x7F800000); cur = b;
                }
                float v = sC[m * CS + tid] + blc;
                float y = fmaxf((v - s_mu[m]) * s_rs[m] * gc + bc, 0.f);
                s += y; mx = fmaxf(mx, y);
            }
            atomicAdd(&d_psum[cur * HH + tid], s);
            atomicMax((int*)&d_pmax[cur * HH + tid], __float_as_int(mx));
        }
    } else {
        for (int idx = tid; idx < 128 * 32; idx += 256) {
            int m = idx >> 5, q = idx & 31;
            int n = n0 + m;
            if (n >= NN) continue;
            float mu = s_mu[m], rs = s_rs[m];
            float4 v = *(const float4*)&sC[m * CS + q * 4];
            float y0 = fmaxf((v.x + s_bl[q*4+0] - mu) * rs * s_g[q*4+0] + s_bn[q*4+0], 0.f);
            float y1 = fmaxf((v.y + s_bl[q*4+1] - mu) * rs * s_g[q*4+1] + s_bn[q*4+1], 0.f);
            float y2 = fmaxf((v.z + s_bl[q*4+2] - mu) * rs * s_g[q*4+2] + s_bn[q*4+2], 0.f);
            float y3 = fmaxf((v.w + s_bl[q*4+3] - mu) * rs * s_g[q*4+3] + s_bn[q*4+3], 0.f);
            *(float4*)&hout[(size_t)n * HH + q * 4] = make_float4(y0, y1, y2, y3);
        }
    }
}

__global__ void k_cnt(const int* __restrict__ batch) {
    int n = blockIdx.x * blockDim.x + threadIdx.x;
    if (n < NN) atomicAdd(&d_cnt[batch[n]], 1.f);
}

__global__ void __launch_bounds__(64)
k_mlp(const float* __restrict__ Wf0, const float* __restrict__ bf0,
      const float* __restrict__ Wf1, const float* __restrict__ bf1,
      const float* __restrict__ Wf2, const float* __restrict__ bf2,
      float* __restrict__ out) {
    __shared__ float z[2 * HH];
    __shared__ float t1[50];
    __shared__ float t2[50];
    int gg = blockIdx.x;
    int t = threadIdx.x;

    float c = fmaxf(d_cnt[gg], 1.f);
    for (int d = t; d < 2 * HH; d += 64)
        z[d] = (d < HH) ? d_psum[gg * HH + d] / c : d_pmax[gg * HH + (d - HH)];
    __syncthreads();

    if (t < 50) {
        float s = bf0[t];
        for (int k = 0; k < 2 * HH; k++) s += z[k] * Wf0[k * 50 + t];
        t1[t] = fmaxf(s, 0.f);
    }
    __syncthreads();
    if (t < 50) {
        float s = bf1[t];
        for (int k = 0; k < 50; k++) s += t1[k] * Wf1[k * 50 + t];
        t2[t] = fmaxf(s, 0.f);
    }
    __syncthreads();
    if (t < 10) {
        float s = bf2[t];
        for (int k = 0; k < 50; k++) s += t2[k] * Wf2[k * 10 + t];
        out[gg * 10 + t] = fmaxf(s, 0.f);
    }
}

// ---------------------------------------------------------------------------
static inline int cdiv(long long a, int b) { return (int)((a + b - 1) / b); }

extern "C" void kernel_launch(void* const* d_in, const int* in_sizes, int n_in,
                              void* d_out, int out_size) {
    const float* x      = (const float*)d_in[0];
    const float* xdims  = (const float*)d_in[1];
    const int*   st     = (const int*)d_in[2];
    const int*   ei     = (const int*)d_in[3];
    const int*   batch  = (const int*)d_in[4];
    const float* emb    = (const float*)d_in[5];
    const float* Wl0 = (const float*)d_in[6];
    const float* bl0 = (const float*)d_in[7];
    const float* Wr0 = (const float*)d_in[8];
    const float* g0  = (const float*)d_in[9];
    const float* bn0 = (const float*)d_in[10];
    const float* Wl1 = (const float*)d_in[11];
    const float* bl1 = (const float*)d_in[12];
    const float* Wr1 = (const float*)d_in[13];
    const float* g1  = (const float*)d_in[14];
    const float* bn1 = (const float*)d_in[15];
    const float* Wf0 = (const float*)d_in[16];
    const float* bf0 = (const float*)d_in[17];
    const float* Wf1 = (const float*)d_in[18];
    const float* bf1 = (const float*)d_in[19];
    const float* Wf2 = (const float*)d_in[20];
    const float* bf2 = (const float*)d_in[21];
    float* out = (float*)d_out;

    const int* src = ei;
    const int* dst = ei + EE;

    float* p_h0 = nullptr;
    float* p_h1 = nullptr;
    float* p_agg = nullptr;
    cudaGetSymbolAddress((void**)&p_h0, d_h0);
    cudaGetSymbolAddress((void**)&p_h1, d_h1);
    cudaGetSymbolAddress((void**)&p_agg, d_agg);

    const int SMEMSZ = 128 * CS * 4 + 6 * 512;   // 67584 + 3072 = 70656
    cudaFuncSetAttribute((const void*)k_sage_hmma<KP0, KR0, false>,
                         cudaFuncAttributeMaxDynamicSharedMemorySize, SMEMSZ);
    cudaFuncSetAttribute((const void*)k_sage_hmma<HH, HH, true>,
                         cudaFuncAttributeMaxDynamicSharedMemorySize, SMEMSZ);

    // init + node features + CSR build (shared by both layers)
    k_init0<<<cdiv(NN, 256), 256>>>();
    k_build_h0<<<cdiv((long long)NN * KP0, 256), 256>>>(x, xdims, st, emb);
    k_deg<<<cdiv(EE, 256), 256>>>(dst);
    k_scan1<<<NSB, SCAN_B>>>();
    k_scan2<<<1, 32>>>();
    k_scan3<<<cdiv(NN, 256), 256>>>();
    k_fill<<<cdiv(EE, 256), 256>>>(src, dst);
    k_cnt<<<cdiv(NN, 256), 256>>>(batch);

    // ---- layer 0 ----
    k_gatherv<KP0><<<cdiv(NN, 4), 128>>>(p_h0);
    k_sage_hmma<KP0, KR0, false><<<cdiv(NN, 128), 256, SMEMSZ>>>(
        Wl0, bl0, Wr0, g0, bn0, p_agg, p_h0, p_h1, nullptr);

    // ---- layer 1 (pooling fused into epilogue) ----
    k_gatherv<HH><<<cdiv(NN, 4), 128>>>(p_h1);
    k_sage_hmma<HH, HH, true><<<cdiv(NN, 128), 256, SMEMSZ>>>(
        Wl1, bl1, Wr1, g1, bn1, p_agg, p_h1, nullptr, batch);

    // ---- MLP head ----
    k_mlp<<<GG, 64>>>(Wf0, bf0, Wf1, bf1, Wf2, bf2, out);
}

// round 7
// speedup vs baseline: 3.6859x; 1.3879x over previous
#include <cuda_runtime.h>
#include <cuda_bf16.h>
#include <math.h>
#include <stdint.h>

#define NN 100000
#define EE 600000
#define GG 512
#define HH 128
#define KP0 80          // layer0 K padded (74 -> 80)
#define KR0 74
#define SCAN_B 512
#define NSB ((NN + SCAN_B - 1) / SCAN_B)   // 196
#define CS 132          // smem C row stride (floats)

// ---- scratch (device globals; no allocation allowed) ----
__device__ __nv_bfloat16 d_h0hi[NN * KP0];
__device__ __nv_bfloat16 d_h0lo[NN * KP0];
__device__ __nv_bfloat16 d_h1hi[NN * HH];
__device__ __nv_bfloat16 d_h1lo[NN * HH];
__device__ __nv_bfloat16 d_agghi[NN * HH];
__device__ __nv_bfloat16 d_agglo[NN * HH];
__device__ __nv_bfloat16 d_whi[256 * HH];
__device__ __nv_bfloat16 d_wlo[256 * HH];
__device__ float d_invdeg[NN];
__device__ int   d_degi[NN];
__device__ int   d_cursor[NN];
__device__ int   d_rowstart[NN + 1];
__device__ int   d_eid[EE];
__device__ int   d_bsum[NSB];
__device__ int   d_boff[NSB];
__device__ float d_psum[GG * HH];
__device__ float d_pmax[GG * HH];
__device__ float d_cnt[GG];

// ============================ helpers ======================================
__device__ __forceinline__ uint32_t smem_u32(const void* p) {
    uint32_t a;
    asm("{ .reg .u64 t; cvta.to.shared.u64 t, %1; cvt.u32.u64 %0, t; }"
        : "=r"(a) : "l"(p));
    return a;
}
__device__ __forceinline__ uint32_t sw128(uint32_t off) { return off ^ ((off >> 3) & 0x70); }
__device__ __forceinline__ uint32_t bpack(__nv_bfloat16 a, __nv_bfloat16 b) {
    return ((uint32_t)__bfloat16_as_ushort(b) << 16) | (uint32_t)__bfloat16_as_ushort(a);
}
__device__ __forceinline__ void ldsm4(uint32_t& r0, uint32_t& r1,
                                      uint32_t& r2, uint32_t& r3, uint32_t addr) {
    asm volatile("ldmatrix.sync.aligned.m8n8.x4.shared.b16 {%0,%1,%2,%3}, [%4];"
                 : "=r"(r0), "=r"(r1), "=r"(r2), "=r"(r3) : "r"(addr));
}
__device__ __forceinline__ void mma16816(float* d, const uint32_t* a,
                                         uint32_t b0, uint32_t b1) {
    asm volatile("mma.sync.aligned.m16n8k16.row.col.f32.bf16.bf16.f32 "
                 "{%0,%1,%2,%3}, {%4,%5,%6,%7}, {%8,%9}, {%0,%1,%2,%3};"
                 : "+f"(d[0]), "+f"(d[1]), "+f"(d[2]), "+f"(d[3])
                 : "r"(a[0]), "r"(a[1]), "r"(a[2]), "r"(a[3]), "r"(b0), "r"(b1));
}
__device__ __forceinline__ float2 b2f2(uint32_t u) {
    return __bfloat1622float2(*reinterpret_cast<__nv_bfloat162*>(&u));
}

// ===========================================================================
__global__ void k_init0() {
    int i = blockIdx.x * blockDim.x + threadIdx.x;
    if (i < NN) { d_degi[i] = 0; d_cursor[i] = 0; }
    if (i < GG * HH) { d_psum[i] = 0.f; d_pmax[i] = __int_as_float(0xFF800000); }
    if (i < GG) d_cnt[i] = 0.f;
}

__global__ void k_build_h0(const float* __restrict__ x,
                           const float* __restrict__ xd,
                           const int* __restrict__ st,
                           const float* __restrict__ emb) {
    int idx = blockIdx.x * blockDim.x + threadIdx.x;
    if (idx >= NN * KP0) return;
    int n = idx / KP0;
    int j = idx - n * KP0;
    float v;
    if (j < 60)      v = x[n * 60 + j];
    else if (j < 62) v = xd[n * 2 + (j - 60)];
    else if (j < 74) v = emb[st[n] * 12 + (j - 62)];
    else             v = 0.f;
    __nv_bfloat16 hi = __float2bfloat16(v);
    d_h0hi[idx] = hi;
    d_h0lo[idx] = __float2bfloat16(v - __bfloat162float(hi));
}

// pre-split weights into [o][KT] bf16 hi/lo (done once per layer)
template <int KP, int KREAL>
__global__ void k_prepw(const float* __restrict__ Wl, const float* __restrict__ Wr) {
    constexpr int KT = 2 * KP;
    int idx = blockIdx.x * blockDim.x + threadIdx.x;
    if (idx >= HH * KT) return;
    int o = idx / KT;
    int k = idx - o * KT;
    float w = 0.f;
    const float* W = (k < KP) ? Wl : Wr;
    int r = (k < KP) ? k : k - KP;
    if (r < KREAL) w = W[(size_t)r * HH + o];
    __nv_bfloat16 hi = __float2bfloat16(w);
    d_whi[idx] = hi;
    d_wlo[idx] = __float2bfloat16(w - __bfloat162float(hi));
}

__global__ void k_deg(const int* __restrict__ dst) {
    int e = blockIdx.x * blockDim.x + threadIdx.x;
    if (e < EE) atomicAdd(&d_degi[dst[e]], 1);
}

__global__ void __launch_bounds__(SCAN_B)
k_scan1() {
    __shared__ int sc[SCAN_B];
    int tid = threadIdx.x;
    int i = blockIdx.x * SCAN_B + tid;
    int v = (i < NN) ? d_degi[i] : 0;
    sc[tid] = v;
    __syncthreads();
#pragma unroll
    for (int off = 1; off < SCAN_B; off <<= 1) {
        int t = (tid >= off) ? sc[tid - off] : 0;
        __syncthreads();
        sc[tid] += t;
        __syncthreads();
    }
    if (i < NN) {
        d_rowstart[i] = sc[tid] - v;
        d_invdeg[i] = 1.f / fmaxf((float)v, 1.f);
    }
    if (tid == SCAN_B - 1) d_bsum[blockIdx.x] = sc[tid];
}

__global__ void k_scan2() {
    if (threadIdx.x == 0 && blockIdx.x == 0) {
        int run = 0;
        for (int b = 0; b < NSB; b++) { d_boff[b] = run; run += d_bsum[b]; }
        d_rowstart[NN] = EE;
    }
}

__global__ void k_scan3() {
    int i = blockIdx.x * blockDim.x + threadIdx.x;
    if (i < NN) d_rowstart[i] += d_boff[i / SCAN_B];
}

__global__ void k_fill(const int* __restrict__ src, const int* __restrict__ dst) {
    int e = blockIdx.x * blockDim.x + threadIdx.x;
    if (e >= EE) return;
    int dn = dst[e];
    int pos = d_rowstart[dn] + atomicAdd(&d_cursor[dn], 1);
    d_eid[pos] = src[e];
}

// gather aggregation from hi/lo bf16 input; emits agg*invdeg as hi/lo bf16.
template <int KP>
__global__ void __launch_bounds__(128)
k_gatherb(const __nv_bfloat16* __restrict__ hhi,
          const __nv_bfloat16* __restrict__ hlo) {
    int n = blockIdx.x * 4 + (threadIdx.x >> 5);
    int lane = threadIdx.x & 31;
    if (n >= NN) return;
    constexpr int C4 = KP / 4;
    if (lane >= C4) return;
    int s = d_rowstart[n];
    int e = d_rowstart[n + 1];
    float a0 = 0.f, a1 = 0.f, a2 = 0.f, a3 = 0.f;
    for (int j = s; j < e; j++) {
        int id = d_eid[j];
        size_t off = (size_t)id * KP + lane * 4;
        uint2 vh = *(const uint2*)&hhi[off];
        uint2 vl = *(const uint2*)&hlo[off];
        float2 h01 = b2f2(vh.x), h23 = b2f2(vh.y);
        float2 l01 = b2f2(vl.x), l23 = b2f2(vl.y);
        a0 += h01.x + l01.x; a1 += h01.y + l01.y;
        a2 += h23.x + l23.x; a3 += h23.y + l23.y;
    }
    float inv = d_invdeg[n];
    a0 *= inv; a1 *= inv; a2 *= inv; a3 *= inv;
    __nv_bfloat16 b0 = __float2bfloat16(a0), b1 = __float2bfloat16(a1);
    __nv_bfloat16 b2 = __float2bfloat16(a2), b3 = __float2bfloat16(a3);
    size_t oo = (size_t)n * KP + lane * 4;
    *(uint2*)&d_agghi[oo] = make_uint2(bpack(b0, b1), bpack(b2, b3));
    *(uint2*)&d_agglo[oo] = make_uint2(
        bpack(__float2bfloat16(a0 - __bfloat162float(b0)),
              __float2bfloat16(a1 - __bfloat162float(b1))),
        bpack(__float2bfloat16(a2 - __bfloat162float(b2)),
              __float2bfloat16(a3 - __bfloat162float(b3))));
}

// ===========================================================================
// HMMA fused SAGE layer, pure-copy staging (all operands pre-split bf16).
// Tile 128 nodes x 128 outs, K chunks of 64; 8 warps (2x4 warp grid).
// ===========================================================================
template <int KP, bool POOL>
__global__ void __launch_bounds__(256, 1)
k_sage_hmma(const float* __restrict__ bl, const float* __restrict__ g,
            const float* __restrict__ bn,
            const __nv_bfloat16* __restrict__ hhi,
            const __nv_bfloat16* __restrict__ hlo,
            __nv_bfloat16* __restrict__ outhi,
            __nv_bfloat16* __restrict__ outlo,
            const int* __restrict__ batch) {
    extern __shared__ __align__(128) char smem[];
    constexpr int KT = 2 * KP;
    constexpr int NCH = (KT + 63) / 64;
    const uint32_t sb = smem_u32(smem);
    const int tid = threadIdx.x;
    const int wid = tid >> 5;
    const int lid = tid & 31;
    const int n0 = blockIdx.x * 128;
    const int wm = wid & 1;
    const int wn = wid >> 1;

    const uint32_t AHI = sb, ALO = sb + 16384, BHI = sb + 32768, BLO = sb + 49152;
    float* sC   = (float*)smem;
    float* s_bl = (float*)(smem + 128 * CS * 4);
    float* s_g  = s_bl + 128;
    float* s_bn = s_bl + 256;
    float* s_mu = s_bl + 384;
    float* s_rs = s_bl + 512;
    int*  sbat  = (int*)(s_bl + 640);

    if (tid < 128) {
        s_bl[tid] = bl[tid]; s_g[tid] = g[tid]; s_bn[tid] = bn[tid];
        if (POOL) sbat[tid] = (n0 + tid < NN) ? batch[n0 + tid] : 0;
    }

    float acc[4][4][4];
#pragma unroll
    for (int mt = 0; mt < 4; mt++)
#pragma unroll
        for (int nt = 0; nt < 4; nt++)
#pragma unroll
            for (int j = 0; j < 4; j++) acc[mt][nt][j] = 0.f;

    for (int c = 0; c < NCH; c++) {
        const int kbase = c * 64;
        __syncthreads();
        // ---- stage A (pure copy, swizzled): 128 rows x 64 k, hi+lo ----
#pragma unroll
        for (int it = 0; it < 4; it++) {
            int idx = tid + it * 256;
            int m = idx >> 3, j = idx & 7;
            int kg = kbase + j * 8;
            int n = n0 + m;
            uint4 vh = make_uint4(0, 0, 0, 0), vl = make_uint4(0, 0, 0, 0);
            if (n < NN && kg < KT) {
                size_t off = (kg < KP) ? ((size_t)n * KP + kg)
                                       : ((size_t)n * KP + kg - KP);
                const __nv_bfloat16* ph = (kg < KP) ? d_agghi : hhi;
                const __nv_bfloat16* pl = (kg < KP) ? d_agglo : hlo;
                vh = *(const uint4*)&ph[off];
                vl = *(const uint4*)&pl[off];
            }
            uint32_t sw = sw128((uint32_t)m * 128 + j * 16);
            *(uint4*)(smem + 0     + sw) = vh;
            *(uint4*)(smem + 16384 + sw) = vl;
        }
        // ---- stage B (pure copy, swizzled): 128 outs x 64 k, hi+lo ----
#pragma unroll
        for (int it = 0; it < 4; it++) {
            int idx = tid + it * 256;
            int o = idx >> 3, j = idx & 7;
            int kg = kbase + j * 8;
            uint4 vh = make_uint4(0, 0, 0, 0), vl = make_uint4(0, 0, 0, 0);
            if (kg < KT) {
                size_t off = (size_t)o * KT + kg;
                vh = *(const uint4*)&d_whi[off];
                vl = *(const uint4*)&d_wlo[off];
            }
            uint32_t sw = sw128((uint32_t)o * 128 + j * 16);
            *(uint4*)(smem + 32768 + sw) = vh;
            *(uint4*)(smem + 49152 + sw) = vl;
        }
        __syncthreads();
        // ---- compute k16-steps ----
        const int steps = min(4, (KT - kbase) / 16);
#pragma unroll
        for (int ks = 0; ks < 4; ks++) {
            if (ks >= steps) break;
            const int kof = ks * 16 + (((lid >> 4) & 1) << 3);
            const int rsub = (lid & 7) + ((lid >> 3) & 1) * 8;

            uint32_t ah[4][4], al[4][4];
#pragma unroll
            for (int mt = 0; mt < 4; mt++) {
                int row = wm * 64 + mt * 16 + rsub;
                uint32_t o = sw128((uint32_t)row * 128 + kof * 2);
                ldsm4(ah[mt][0], ah[mt][1], ah[mt][2], ah[mt][3], AHI + o);
                ldsm4(al[mt][0], al[mt][1], al[mt][2], al[mt][3], ALO + o);
            }
            uint32_t bh[2][4], blo[2][4];
#pragma unroll
            for (int ng = 0; ng < 2; ng++) {
                int rown = wn * 32 + ng * 16 + rsub;
                uint32_t o = sw128((uint32_t)rown * 128 + kof * 2);
                ldsm4(bh[ng][0], bh[ng][1], bh[ng][2], bh[ng][3], BHI + o);
                ldsm4(blo[ng][0], blo[ng][1], blo[ng][2], blo[ng][3], BLO + o);
            }
#pragma unroll
            for (int mt = 0; mt < 4; mt++)
#pragma unroll
                for (int nt = 0; nt < 4; nt++) {
                    int ng = nt >> 1, sel = nt & 1;
                    mma16816(acc[mt][nt], ah[mt], bh[ng][sel], bh[ng][sel + 2]);
                    mma16816(acc[mt][nt], ah[mt], blo[ng][sel], blo[ng][sel + 2]);
                    mma16816(acc[mt][nt], al[mt], bh[ng][sel], bh[ng][sel + 2]);
                }
        }
    }
    __syncthreads();

    // ---- store C frags to smem ----
#pragma unroll
    for (int mt = 0; mt < 4; mt++)
#pragma unroll
        for (int nt = 0; nt < 4; nt++) {
            int r0 = wm * 64 + mt * 16 + (lid >> 2);
            int c0 = wn * 32 + nt * 8 + 2 * (lid & 3);
            sC[r0 * CS + c0]           = acc[mt][nt][0];
            sC[r0 * CS + c0 + 1]       = acc[mt][nt][1];
            sC[(r0 + 8) * CS + c0]     = acc[mt][nt][2];
            sC[(r0 + 8) * CS + c0 + 1] = acc[mt][nt][3];
        }
    __syncthreads();

    // ---- LN stats per node row ----
    if (tid < 128) {
        float sum = 0.f, sq = 0.f;
        for (int cc = 0; cc < 128; cc++) {
            float v = sC[tid * CS + cc] + s_bl[cc];
            sum += v; sq += v * v;
        }
        float mu = sum * (1.f / HH);
        float var = fmaxf(sq * (1.f / HH) - mu * mu, 0.f);
        s_mu[tid] = mu;
        s_rs[tid] = rsqrtf(var + 1e-5f);
    }
    __syncthreads();

    if (POOL) {
        if (tid < 128) {
            int vrows = min(128, NN - n0);
            float gc = s_g[tid], bc = s_bn[tid], blc = s_bl[tid];
            float s = 0.f, mx = -__int_as_float(0x7F800000);
            int cur = sbat[0];
            for (int m = 0; m < vrows; m++) {
                int b = sbat[m];
                if (b != cur) {
                    atomicAdd(&d_psum[cur * HH + tid], s);
                    atomicMax((int*)&d_pmax[cur * HH + tid], __float_as_int(mx));
                    s = 0.f; mx = -__int_as_float(0x7F800000); cur = b;
                }
                float v = sC[m * CS + tid] + blc;
                float y = fmaxf((v - s_mu[m]) * s_rs[m] * gc + bc, 0.f);
                s += y; mx = fmaxf(mx, y);
            }
            atomicAdd(&d_psum[cur * HH + tid], s);
            atomicMax((int*)&d_pmax[cur * HH + tid], __float_as_int(mx));
        }
    } else {
        for (int idx = tid; idx < 128 * 32; idx += 256) {
            int m = idx >> 5, q = idx & 31;
            int n = n0 + m;
            if (n >= NN) continue;
            float mu = s_mu[m], rs = s_rs[m];
            float4 v = *(const float4*)&sC[m * CS + q * 4];
            float y0 = fmaxf((v.x + s_bl[q*4+0] - mu) * rs * s_g[q*4+0] + s_bn[q*4+0], 0.f);
            float y1 = fmaxf((v.y + s_bl[q*4+1] - mu) * rs * s_g[q*4+1] + s_bn[q*4+1], 0.f);
            float y2 = fmaxf((v.z + s_bl[q*4+2] - mu) * rs * s_g[q*4+2] + s_bn[q*4+2], 0.f);
            float y3 = fmaxf((v.w + s_bl[q*4+3] - mu) * rs * s_g[q*4+3] + s_bn[q*4+3], 0.f);
            __nv_bfloat16 h0 = __float2bfloat16(y0), h1 = __float2bfloat16(y1);
            __nv_bfloat16 h2 = __float2bfloat16(y2), h3 = __float2bfloat16(y3);
            size_t oo = (size_t)n * HH + q * 4;
            *(uint2*)&outhi[oo] = make_uint2(bpack(h0, h1), bpack(h2, h3));
            *(uint2*)&outlo[oo] = make_uint2(
                bpack(__float2bfloat16(y0 - __bfloat162float(h0)),
                      __float2bfloat16(y1 - __bfloat162float(h1))),
                bpack(__float2bfloat16(y2 - __bfloat162float(h2)),
                      __float2bfloat16(y3 - __bfloat162float(h3))));
        }
    }
}

__global__ void k_cnt(const int* __restrict__ batch) {
    int n = blockIdx.x * blockDim.x + threadIdx.x;
    if (n < NN) atomicAdd(&d_cnt[batch[n]], 1.f);
}

__global__ void __launch_bounds__(64)
k_mlp(const float* __restrict__ Wf0, const float* __restrict__ bf0,
      const float* __restrict__ Wf1, const float* __restrict__ bf1,
      const float* __restrict__ Wf2, const float* __restrict__ bf2,
      float* __restrict__ out) {
    __shared__ float z[2 * HH];
    __shared__ float t1[50];
    __shared__ float t2[50];
    int gg = blockIdx.x;
    int t = threadIdx.x;

    float c = fmaxf(d_cnt[gg], 1.f);
    for (int d = t; d < 2 * HH; d += 64)
        z[d] = (d < HH) ? d_psum[gg * HH + d] / c : d_pmax[gg * HH + (d - HH)];
    __syncthreads();

    if (t < 50) {
        float s = bf0[t];
        for (int k = 0; k < 2 * HH; k++) s += z[k] * Wf0[k * 50 + t];
        t1[t] = fmaxf(s, 0.f);
    }
    __syncthreads();
    if (t < 50) {
        float s = bf1[t];
        for (int k = 0; k < 50; k++) s += t1[k] * Wf1[k * 50 + t];
        t2[t] = fmaxf(s, 0.f);
    }
    __syncthreads();
    if (t < 10) {
        float s = bf2[t];
        for (int k = 0; k < 50; k++) s += t2[k] * Wf2[k * 10 + t];
        out[gg * 10 + t] = fmaxf(s, 0.f);
    }
}

// ---------------------------------------------------------------------------
static inline int cdiv(long long a, int b) { return (int)((a + b - 1) / b); }

extern "C" void kernel_launch(void* const* d_in, const int* in_sizes, int n_in,
                              void* d_out, int out_size) {
    const float* x      = (const float*)d_in[0];
    const float* xdims  = (const float*)d_in[1];
    const int*   st     = (const int*)d_in[2];
    const int*   ei     = (const int*)d_in[3];
    const int*   batch  = (const int*)d_in[4];
    const float* emb    = (const float*)d_in[5];
    const float* Wl0 = (const float*)d_in[6];
    const float* bl0 = (const float*)d_in[7];
    const float* Wr0 = (const float*)d_in[8];
    const float* g0  = (const float*)d_in[9];
    const float* bn0 = (const float*)d_in[10];
    const float* Wl1 = (const float*)d_in[11];
    const float* bl1 = (const float*)d_in[12];
    const float* Wr1 = (const float*)d_in[13];
    const float* g1  = (const float*)d_in[14];
    const float* bn1 = (const float*)d_in[15];
    const float* Wf0 = (const float*)d_in[16];
    const float* bf0 = (const float*)d_in[17];
    const float* Wf1 = (const float*)d_in[18];
    const float* bf1 = (const float*)d_in[19];
    const float* Wf2 = (const float*)d_in[20];
    const float* bf2 = (const float*)d_in[21];
    float* out = (float*)d_out;

    const int* src = ei;
    const int* dst = ei + EE;

    __nv_bfloat16 *p_h0hi, *p_h0lo, *p_h1hi, *p_h1lo;
    cudaGetSymbolAddress((void**)&p_h0hi, d_h0hi);
    cudaGetSymbolAddress((void**)&p_h0lo, d_h0lo);
    cudaGetSymbolAddress((void**)&p_h1hi, d_h1hi);
    cudaGetSymbolAddress((void**)&p_h1lo, d_h1lo);

    const int SMEMSZ = 128 * CS * 4 + 6 * 512;   // 70656
    cudaFuncSetAttribute((const void*)k_sage_hmma<KP0, false>,
                         cudaFuncAttributeMaxDynamicSharedMemorySize, SMEMSZ);
    cudaFuncSetAttribute((const void*)k_sage_hmma<HH, true>,
                         cudaFuncAttributeMaxDynamicSharedMemorySize, SMEMSZ);

    // init + node features + CSR build (shared by both layers)
    k_init0<<<cdiv(NN, 256), 256>>>();
    k_build_h0<<<cdiv((long long)NN * KP0, 256), 256>>>(x, xdims, st, emb);
    k_deg<<<cdiv(EE, 256), 256>>>(dst);
    k_scan1<<<NSB, SCAN_B>>>();
    k_scan2<<<1, 32>>>();
    k_scan3<<<cdiv(NN, 256), 256>>>();
    k_fill<<<cdiv(EE, 256), 256>>>(src, dst);
    k_cnt<<<cdiv(NN, 256), 256>>>(batch);

    // ---- layer 0 ----
    k_prepw<KP0, KR0><<<cdiv(HH * 2 * KP0, 256), 256>>>(Wl0, Wr0);
    k_gatherb<KP0><<<cdiv(NN, 4), 128>>>(p_h0hi, p_h0lo);
    k_sage_hmma<KP0, false><<<cdiv(NN, 128), 256, SMEMSZ>>>(
        bl0, g0, bn0, p_h0hi, p_h0lo, p_h1hi, p_h1lo, nullptr);

    // ---- layer 1 (pooling fused into epilogue) ----
    k_prepw<HH, HH><<<cdiv(HH * 2 * HH, 256), 256>>>(Wl1, Wr1);
    k_gatherb<HH><<<cdiv(NN, 4), 128>>>(p_h1hi, p_h1lo);
    k_sage_hmma<HH, true><<<cdiv(NN, 128), 256, SMEMSZ>>>(
        bl1, g1, bn1, p_h1hi, p_h1lo, nullptr, nullptr, batch);

    // ---- MLP head ----
    k_mlp<<<GG, 64>>>(Wf0, bf0, Wf1, bf1, Wf2, bf2, out);
}

// round 8
// speedup vs baseline: 4.4530x; 1.2081x over previous
#include <cuda_runtime.h>
#include <cuda_bf16.h>
#include <math.h>
#include <stdint.h>

#define NN 100000
#define EE 600000
#define GG 512
#define HH 128
#define KP0 80          // layer0 K padded (74 -> 80)
#define KR0 74
#define SCAN_B 512
#define NSB ((NN + SCAN_B - 1) / SCAN_B)   // 196
#define CS 132          // smem C row stride (floats)

// ---- scratch (device globals; no allocation allowed) ----
// packed layout: per node, per 4-channel group q: uint4{hi01, hi23, lo01, lo23}
__device__ uint4 d_h0p[NN * (KP0 / 4)];
__device__ uint4 d_h1p[NN * (HH / 4)];
__device__ uint4 d_aggp[NN * (HH / 4)];
__device__ __nv_bfloat16 d_whi[256 * HH];
__device__ __nv_bfloat16 d_wlo[256 * HH];
__device__ float d_invdeg[NN];
__device__ int   d_degi[NN];
__device__ int   d_cursor[NN];
__device__ int   d_rowstart[NN + 1];
__device__ int   d_eid[EE];
__device__ int   d_bsum[NSB];
__device__ int   d_boff[NSB];
__device__ float d_psum[GG * HH];
__device__ float d_pmax[GG * HH];
__device__ float d_cnt[GG];

// ============================ helpers ======================================
__device__ __forceinline__ uint32_t smem_u32(const void* p) {
    uint32_t a;
    asm("{ .reg .u64 t; cvta.to.shared.u64 t, %1; cvt.u32.u64 %0, t; }"
        : "=r"(a) : "l"(p));
    return a;
}
__device__ __forceinline__ uint32_t sw128(uint32_t off) { return off ^ ((off >> 3) & 0x70); }
__device__ __forceinline__ uint32_t bpack(__nv_bfloat16 a, __nv_bfloat16 b) {
    return ((uint32_t)__bfloat16_as_ushort(b) << 16) | (uint32_t)__bfloat16_as_ushort(a);
}
__device__ __forceinline__ void ldsm4(uint32_t& r0, uint32_t& r1,
                                      uint32_t& r2, uint32_t& r3, uint32_t addr) {
    asm volatile("ldmatrix.sync.aligned.m8n8.x4.shared.b16 {%0,%1,%2,%3}, [%4];"
                 : "=r"(r0), "=r"(r1), "=r"(r2), "=r"(r3) : "r"(addr));
}
__device__ __forceinline__ void mma16816(float* d, const uint32_t* a,
                                         uint32_t b0, uint32_t b1) {
    asm volatile("mma.sync.aligned.m16n8k16.row.col.f32.bf16.bf16.f32 "
                 "{%0,%1,%2,%3}, {%4,%5,%6,%7}, {%8,%9}, {%0,%1,%2,%3};"
                 : "+f"(d[0]), "+f"(d[1]), "+f"(d[2]), "+f"(d[3])
                 : "r"(a[0]), "r"(a[1]), "r"(a[2]), "r"(a[3]), "r"(b0), "r"(b1));
}
__device__ __forceinline__ float2 b2f2(uint32_t u) {
    return __bfloat1622float2(*reinterpret_cast<__nv_bfloat162*>(&u));
}
// split 4 fp32 into packed uint4 {hi01, hi23, lo01, lo23}
__device__ __forceinline__ uint4 pack4(float a0, float a1, float a2, float a3) {
    __nv_bfloat16 b0 = __float2bfloat16(a0), b1 = __float2bfloat16(a1);
    __nv_bfloat16 b2 = __float2bfloat16(a2), b3 = __float2bfloat16(a3);
    uint4 r;
    r.x = bpack(b0, b1);
    r.y = bpack(b2, b3);
    r.z = bpack(__float2bfloat16(a0 - __bfloat162float(b0)),
                __float2bfloat16(a1 - __bfloat162float(b1)));
    r.w = bpack(__float2bfloat16(a2 - __bfloat162float(b2)),
                __float2bfloat16(a3 - __bfloat162float(b3)));
    return r;
}

// ===========================================================================
__global__ void k_init0() {
    int i = blockIdx.x * blockDim.x + threadIdx.x;
    if (i < NN) { d_degi[i] = 0; d_cursor[i] = 0; }
    if (i < GG * HH) { d_psum[i] = 0.f; d_pmax[i] = __int_as_float(0xFF800000); }
    if (i < GG) d_cnt[i] = 0.f;
}

// build packed h0: thread per (node, 4-channel group)
__global__ void k_build_h0(const float* __restrict__ x,
                           const float* __restrict__ xd,
                           const int* __restrict__ st,
                           const float* __restrict__ emb) {
    int idx = blockIdx.x * blockDim.x + threadIdx.x;
    constexpr int C4 = KP0 / 4;
    if (idx >= NN * C4) return;
    int n = idx / C4;
    int q = idx - n * C4;
    float v[4];
#pragma unroll
    for (int t = 0; t < 4; t++) {
        int j = q * 4 + t;
        if (j < 60)      v[t] = x[n * 60 + j];
        else if (j < 62) v[t] = xd[n * 2 + (j - 60)];
        else if (j < 74) v[t] = emb[st[n] * 12 + (j - 62)];
        else             v[t] = 0.f;
    }
    d_h0p[idx] = pack4(v[0], v[1], v[2], v[3]);
}

// pre-split weights into [o][KT] bf16 hi/lo (done once per layer)
template <int KP, int KREAL>
__global__ void k_prepw(const float* __restrict__ Wl, const float* __restrict__ Wr) {
    constexpr int KT = 2 * KP;
    int idx = blockIdx.x * blockDim.x + threadIdx.x;
    if (idx >= HH * KT) return;
    int o = idx / KT;
    int k = idx - o * KT;
    float w = 0.f;
    const float* W = (k < KP) ? Wl : Wr;
    int r = (k < KP) ? k : k - KP;
    if (r < KREAL) w = W[(size_t)r * HH + o];
    __nv_bfloat16 hi = __float2bfloat16(w);
    d_whi[idx] = hi;
    d_wlo[idx] = __float2bfloat16(w - __bfloat162float(hi));
}

__global__ void k_deg(const int* __restrict__ dst) {
    int e = blockIdx.x * blockDim.x + threadIdx.x;
    if (e < EE) atomicAdd(&d_degi[dst[e]], 1);
}

__global__ void __launch_bounds__(SCAN_B)
k_scan1() {
    __shared__ int sc[SCAN_B];
    int tid = threadIdx.x;
    int i = blockIdx.x * SCAN_B + tid;
    int v = (i < NN) ? d_degi[i] : 0;
    sc[tid] = v;
    __syncthreads();
#pragma unroll
    for (int off = 1; off < SCAN_B; off <<= 1) {
        int t = (tid >= off) ? sc[tid - off] : 0;
        __syncthreads();
        sc[tid] += t;
        __syncthreads();
    }
    if (i < NN) {
        d_rowstart[i] = sc[tid] - v;
        d_invdeg[i] = 1.f / fmaxf((float)v, 1.f);
    }
    if (tid == SCAN_B - 1) d_bsum[blockIdx.x] = sc[tid];
}

__global__ void k_scan2() {
    if (threadIdx.x == 0 && blockIdx.x == 0) {
        int run = 0;
        for (int b = 0; b < NSB; b++) { d_boff[b] = run; run += d_bsum[b]; }
        d_rowstart[NN] = EE;
    }
}

__global__ void k_scan3() {
    int i = blockIdx.x * blockDim.x + threadIdx.x;
    if (i < NN) d_rowstart[i] += d_boff[i / SCAN_B];
}

__global__ void k_fill(const int* __restrict__ src, const int* __restrict__ dst) {
    int e = blockIdx.x * blockDim.x + threadIdx.x;
    if (e >= EE) return;
    int dn = dst[e];
    int pos = d_rowstart[dn] + atomicAdd(&d_cursor[dn], 1);
    d_eid[pos] = src[e];
}

// gather aggregation over packed hi/lo input; emits agg*invdeg packed.
// One warp per node, lane = 4-channel group; edge loop unrolled x2.
template <int KP>
__global__ void __launch_bounds__(128)
k_gatherp(const uint4* __restrict__ hp) {
    int n = blockIdx.x * 4 + (threadIdx.x >> 5);
    int lane = threadIdx.x & 31;
    if (n >= NN) return;
    constexpr int C4 = KP / 4;
    if (lane >= C4) return;
    int s = d_rowstart[n];
    int e = d_rowstart[n + 1];
    float a0 = 0.f, a1 = 0.f, a2 = 0.f, a3 = 0.f;
    int j = s;
    for (; j + 1 < e; j += 2) {
        int id0 = d_eid[j];
        int id1 = d_eid[j + 1];
        uint4 v0 = hp[(size_t)id0 * C4 + lane];
        uint4 v1 = hp[(size_t)id1 * C4 + lane];
        float2 h01 = b2f2(v0.x), h23 = b2f2(v0.y);
        float2 l01 = b2f2(v0.z), l23 = b2f2(v0.w);
        a0 += h01.x + l01.x; a1 += h01.y + l01.y;
        a2 += h23.x + l23.x; a3 += h23.y + l23.y;
        h01 = b2f2(v1.x); h23 = b2f2(v1.y);
        l01 = b2f2(v1.z); l23 = b2f2(v1.w);
        a0 += h01.x + l01.x; a1 += h01.y + l01.y;
        a2 += h23.x + l23.x; a3 += h23.y + l23.y;
    }
    if (j < e) {
        uint4 v0 = hp[(size_t)d_eid[j] * C4 + lane];
        float2 h01 = b2f2(v0.x), h23 = b2f2(v0.y);
        float2 l01 = b2f2(v0.z), l23 = b2f2(v0.w);
        a0 += h01.x + l01.x; a1 += h01.y + l01.y;
        a2 += h23.x + l23.x; a3 += h23.y + l23.y;
    }
    float inv = d_invdeg[n];
    d_aggp[(size_t)n * C4 + lane] = pack4(a0 * inv, a1 * inv, a2 * inv, a3 * inv);
}

// ===========================================================================
// HMMA fused SAGE layer, pure-copy staging from packed hi/lo operands.
// Tile 128 nodes x 128 outs, K chunks of 64; 8 warps (2x4 warp grid).
// ===========================================================================
template <int KP, bool POOL>
__global__ void __launch_bounds__(256, 1)
k_sage_hmma(const float* __restrict__ bl, const float* __restrict__ g,
            const float* __restrict__ bn,
            const uint4* __restrict__ hp,
            uint4* __restrict__ outp,
            const int* __restrict__ batch) {
    extern __shared__ __align__(128) char smem[];
    constexpr int KT = 2 * KP;
    constexpr int NCH = (KT + 63) / 64;
    constexpr int C4 = KP / 4;
    const uint32_t sb = smem_u32(smem);
    const int tid = threadIdx.x;
    const int wid = tid >> 5;
    const int lid = tid & 31;
    const int n0 = blockIdx.x * 128;
    const int wm = wid & 1;
    const int wn = wid >> 1;

    const uint32_t AHI = sb, ALO = sb + 16384, BHI = sb + 32768, BLO = sb + 49152;
    float* sC   = (float*)smem;
    float* s_bl = (float*)(smem + 128 * CS * 4);
    float* s_g  = s_bl + 128;
    float* s_bn = s_bl + 256;
    float* s_mu = s_bl + 384;
    float* s_rs = s_bl + 512;
    int*  sbat  = (int*)(s_bl + 640);

    if (tid < 128) {
        s_bl[tid] = bl[tid]; s_g[tid] = g[tid]; s_bn[tid] = bn[tid];
        if (POOL) sbat[tid] = (n0 + tid < NN) ? batch[n0 + tid] : 0;
    }

    float acc[4][4][4];
#pragma unroll
    for (int mt = 0; mt < 4; mt++)
#pragma unroll
        for (int nt = 0; nt < 4; nt++)
#pragma unroll
            for (int j = 0; j < 4; j++) acc[mt][nt][j] = 0.f;

    for (int c = 0; c < NCH; c++) {
        const int kbase = c * 64;
        __syncthreads();
        // ---- stage A (packed copy, swizzled): 128 rows x 64 k, hi+lo ----
#pragma unroll
        for (int it = 0; it < 4; it++) {
            int idx = tid + it * 256;
            int m = idx >> 3, j = idx & 7;
            int kg = kbase + j * 8;
            int n = n0 + m;
            uint4 vh = make_uint4(0, 0, 0, 0), vl = make_uint4(0, 0, 0, 0);
            if (n < NN && kg < KT) {
                const uint4* P;
                int kl;
                if (kg < KP) { P = d_aggp; kl = kg; } else { P = hp; kl = kg - KP; }
                size_t base = (size_t)n * C4 + (kl >> 2);
                uint4 p0 = P[base], p1 = P[base + 1];
                vh = make_uint4(p0.x, p0.y, p1.x, p1.y);
                vl = make_uint4(p0.z, p0.w, p1.z, p1.w);
            }
            uint32_t sw = sw128((uint32_t)m * 128 + j * 16);
            *(uint4*)(smem + 0     + sw) = vh;
            *(uint4*)(smem + 16384 + sw) = vl;
        }
        // ---- stage B (pure copy, swizzled): 128 outs x 64 k, hi+lo ----
#pragma unroll
        for (int it = 0; it < 4; it++) {
            int idx = tid + it * 256;
            int o = idx >> 3, j = idx & 7;
            int kg = kbase + j * 8;
            uint4 vh = make_uint4(0, 0, 0, 0), vl = make_uint4(0, 0, 0, 0);
            if (kg < KT) {
                size_t off = (size_t)o * KT + kg;
                vh = *(const uint4*)&d_whi[off];
                vl = *(const uint4*)&d_wlo[off];
            }
            uint32_t sw = sw128((uint32_t)o * 128 + j * 16);
            *(uint4*)(smem + 32768 + sw) = vh;
            *(uint4*)(smem + 49152 + sw) = vl;
        }
        __syncthreads();
        // ---- compute k16-steps ----
        const int steps = min(4, (KT - kbase) / 16);
#pragma unroll
        for (int ks = 0; ks < 4; ks++) {
            if (ks >= steps) break;
            const int kof = ks * 16 + (((lid >> 4) & 1) << 3);
            const int rsub = (lid & 7) + ((lid >> 3) & 1) * 8;

            uint32_t ah[4][4], al[4][4];
#pragma unroll
            for (int mt = 0; mt < 4; mt++) {
                int row = wm * 64 + mt * 16 + rsub;
                uint32_t o = sw128((uint32_t)row * 128 + kof * 2);
                ldsm4(ah[mt][0], ah[mt][1], ah[mt][2], ah[mt][3], AHI + o);
                ldsm4(al[mt][0], al[mt][1], al[mt][2], al[mt][3], ALO + o);
            }
            uint32_t bh[2][4], blo[2][4];
#pragma unroll
            for (int ng = 0; ng < 2; ng++) {
                int rown = wn * 32 + ng * 16 + rsub;
                uint32_t o = sw128((uint32_t)rown * 128 + kof * 2);
                ldsm4(bh[ng][0], bh[ng][1], bh[ng][2], bh[ng][3], BHI + o);
                ldsm4(blo[ng][0], blo[ng][1], blo[ng][2], blo[ng][3], BLO + o);
            }
#pragma unroll
            for (int mt = 0; mt < 4; mt++)
#pragma unroll
                for (int nt = 0; nt < 4; nt++) {
                    int ng = nt >> 1, sel = nt & 1;
                    mma16816(acc[mt][nt], ah[mt], bh[ng][sel], bh[ng][sel + 2]);
                    mma16816(acc[mt][nt], ah[mt], blo[ng][sel], blo[ng][sel + 2]);
                    mma16816(acc[mt][nt], al[mt], bh[ng][sel], bh[ng][sel + 2]);
                }
        }
    }
    __syncthreads();

    // ---- store C frags to smem ----
#pragma unroll
    for (int mt = 0; mt < 4; mt++)
#pragma unroll
        for (int nt = 0; nt < 4; nt++) {
            int r0 = wm * 64 + mt * 16 + (lid >> 2);
            int c0 = wn * 32 + nt * 8 + 2 * (lid & 3);
            sC[r0 * CS + c0]           = acc[mt][nt][0];
            sC[r0 * CS + c0 + 1]       = acc[mt][nt][1];
            sC[(r0 + 8) * CS + c0]     = acc[mt][nt][2];
            sC[(r0 + 8) * CS + c0 + 1] = acc[mt][nt][3];
        }
    __syncthreads();

    // ---- LN stats per node row ----
    if (tid < 128) {
        float sum = 0.f, sq = 0.f;
        for (int cc = 0; cc < 128; cc++) {
            float v = sC[tid * CS + cc] + s_bl[cc];
            sum += v; sq += v * v;
        }
        float mu = sum * (1.f / HH);
        float var = fmaxf(sq * (1.f / HH) - mu * mu, 0.f);
        s_mu[tid] = mu;
        s_rs[tid] = rsqrtf(var + 1e-5f);
    }
    __syncthreads();

    if (POOL) {
        if (tid < 128) {
            int vrows = min(128, NN - n0);
            float gc = s_g[tid], bc = s_bn[tid], blc = s_bl[tid];
            float s = 0.f, mx = -__int_as_float(0x7F800000);
            int cur = sbat[0];
            for (int m = 0; m < vrows; m++) {
                int b = sbat[m];
                if (b != cur) {
                    atomicAdd(&d_psum[cur * HH + tid], s);
                    atomicMax((int*)&d_pmax[cur * HH + tid], __float_as_int(mx));
                    s = 0.f; mx = -__int_as_float(0x7F800000); cur = b;
                }
                float v = sC[m * CS + tid] + blc;
                float y = fmaxf((v - s_mu[m]) * s_rs[m] * gc + bc, 0.f);
                s += y; mx = fmaxf(mx, y);
            }
            atomicAdd(&d_psum[cur * HH + tid], s);
            atomicMax((int*)&d_pmax[cur * HH + tid], __float_as_int(mx));
        }
    } else {
        for (int idx = tid; idx < 128 * 32; idx += 256) {
            int m = idx >> 5, q = idx & 31;
            int n = n0 + m;
            if (n >= NN) continue;
            float mu = s_mu[m], rs = s_rs[m];
            float4 v = *(const float4*)&sC[m * CS + q * 4];
            float y0 = fmaxf((v.x + s_bl[q*4+0] - mu) * rs * s_g[q*4+0] + s_bn[q*4+0], 0.f);
            float y1 = fmaxf((v.y + s_bl[q*4+1] - mu) * rs * s_g[q*4+1] + s_bn[q*4+1], 0.f);
            float y2 = fmaxf((v.z + s_bl[q*4+2] - mu) * rs * s_g[q*4+2] + s_bn[q*4+2], 0.f);
            float y3 = fmaxf((v.w + s_bl[q*4+3] - mu) * rs * s_g[q*4+3] + s_bn[q*4+3], 0.f);
            outp[(size_t)n * 32 + q] = pack4(y0, y1, y2, y3);
        }
    }
}

__global__ void k_cnt(const int* __restrict__ batch) {
    int n = blockIdx.x * blockDim.x + threadIdx.x;
    if (n < NN) atomicAdd(&d_cnt[batch[n]], 1.f);
}

__global__ void __launch_bounds__(64)
k_mlp(const float* __restrict__ Wf0, const float* __restrict__ bf0,
      const float* __restrict__ Wf1, const float* __restrict__ bf1,
      const float* __restrict__ Wf2, const float* __restrict__ bf2,
      float* __restrict__ out) {
    __shared__ float z[2 * HH];
    __shared__ float t1[50];
    __shared__ float t2[50];
    int gg = blockIdx.x;
    int t = threadIdx.x;

    float c = fmaxf(d_cnt[gg], 1.f);
    for (int d = t; d < 2 * HH; d += 64)
        z[d] = (d < HH) ? d_psum[gg * HH + d] / c : d_pmax[gg * HH + (d - HH)];
    __syncthreads();

    if (t < 50) {
        float s = bf0[t];
        for (int k = 0; k < 2 * HH; k++) s += z[k] * Wf0[k * 50 + t];
        t1[t] = fmaxf(s, 0.f);
    }
    __syncthreads();
    if (t < 50) {
        float s = bf1[t];
        for (int k = 0; k < 50; k++) s += t1[k] * Wf1[k * 50 + t];
        t2[t] = fmaxf(s, 0.f);
    }
    __syncthreads();
    if (t < 10) {
        float s = bf2[t];
        for (int k = 0; k < 50; k++) s += t2[k] * Wf2[k * 10 + t];
        out[gg * 10 + t] = fmaxf(s, 0.f);
    }
}

// ---------------------------------------------------------------------------
static inline int cdiv(long long a, int b) { return (int)((a + b - 1) / b); }

extern "C" void kernel_launch(void* const* d_in, const int* in_sizes, int n_in,
                              void* d_out, int out_size) {
    const float* x      = (const float*)d_in[0];
    const float* xdims  = (const float*)d_in[1];
    const int*   st     = (const int*)d_in[2];
    const int*   ei     = (const int*)d_in[3];
    const int*   batch  = (const int*)d_in[4];
    const float* emb    = (const float*)d_in[5];
    const float* Wl0 = (const float*)d_in[6];
    const float* bl0 = (const float*)d_in[7];
    const float* Wr0 = (const float*)d_in[8];
    const float* g0  = (const float*)d_in[9];
    const float* bn0 = (const float*)d_in[10];
    const float* Wl1 = (const float*)d_in[11];
    const float* bl1 = (const float*)d_in[12];
    const float* Wr1 = (const float*)d_in[13];
    const float* g1  = (const float*)d_in[14];
    const float* bn1 = (const float*)d_in[15];
    const float* Wf0 = (const float*)d_in[16];
    const float* bf0 = (const float*)d_in[17];
    const float* Wf1 = (const float*)d_in[18];
    const float* bf1 = (const float*)d_in[19];
    const float* Wf2 = (const float*)d_in[20];
    const float* bf2 = (const float*)d_in[21];
    float* out = (float*)d_out;

    const int* src = ei;
    const int* dst = ei + EE;

    uint4 *p_h0p, *p_h1p;
    cudaGetSymbolAddress((void**)&p_h0p, d_h0p);
    cudaGetSymbolAddress((void**)&p_h1p, d_h1p);

    const int SMEMSZ = 128 * CS * 4 + 6 * 512;   // 70656
    cudaFuncSetAttribute((const void*)k_sage_hmma<KP0, false>,
                         cudaFuncAttributeMaxDynamicSharedMemorySize, SMEMSZ);
    cudaFuncSetAttribute((const void*)k_sage_hmma<HH, true>,
                         cudaFuncAttributeMaxDynamicSharedMemorySize, SMEMSZ);

    // init + node features + CSR build (shared by both layers)
    k_init0<<<cdiv(NN, 256), 256>>>();
    k_build_h0<<<cdiv((long long)NN * (KP0 / 4), 256), 256>>>(x, xdims, st, emb);
    k_deg<<<cdiv(EE, 256), 256>>>(dst);
    k_scan1<<<NSB, SCAN_B>>>();
    k_scan2<<<1, 32>>>();
    k_scan3<<<cdiv(NN, 256), 256>>>();
    k_fill<<<cdiv(EE, 256), 256>>>(src, dst);
    k_cnt<<<cdiv(NN, 256), 256>>>(batch);

    // ---- layer 0 ----
    k_prepw<KP0, KR0><<<cdiv(HH * 2 * KP0, 256), 256>>>(Wl0, Wr0);
    k_gatherp<KP0><<<cdiv(NN, 4), 128>>>(p_h0p);
    k_sage_hmma<KP0, false><<<cdiv(NN, 128), 256, SMEMSZ>>>(
        bl0, g0, bn0, p_h0p, p_h1p, nullptr);

    // ---- layer 1 (pooling fused into epilogue) ----
    k_prepw<HH, HH><<<cdiv(HH * 2 * HH, 256), 256>>>(Wl1, Wr1);
    k_gatherp<HH><<<cdiv(NN, 4), 128>>>(p_h1p);
    k_sage_hmma<HH, true><<<cdiv(NN, 128), 256, SMEMSZ>>>(
        bl1, g1, bn1, p_h1p, nullptr, batch);

    // ---- MLP head ----
    k_mlp<<<GG, 64>>>(Wf0, bf0, Wf1, bf1, Wf2, bf2, out);
}